// round 3
// baseline (speedup 1.0000x reference)
#include <cuda_runtime.h>
#include <math.h>
#include <stdint.h>

#define T_  256
#define B_  64
#define H_  768
#define NH_ 12
#define HD_ 64
#define G4H 3072
#define QKVW 2304
#define NTHREADS 256

#define SK_QKV 8     // QKV:   18 n-tiles(128) x 8 = 144 tasks, K=96
#define SK_G   6     // gates: 24 n-tiles(128) x 6 = 144 tasks, K=256
#define SK_F   24    // fuse:   6 n-tiles(128) x 24 = 144 tasks, K=64

// ------------------------- device scratch ----------------------------------
__device__ __align__(256) float g_newvAll[T_*B_*H_];
__device__ __align__(256) float g_qkvp[SK_QKV * 2*B_ * QKVW];
__device__ __align__(256) float g_ctx[B_*2*H_];
__device__ __align__(256) float g_fp[SK_F * B_ * H_];
__device__ __align__(256) float g_gp[SK_G * B_ * G4H];
__device__ __align__(256) float g_base[B_*G4H];
__device__ __align__(256) float g_h[B_*H_];
__device__ __align__(256) float g_c[B_*H_];
__device__ unsigned g_cnt = 0;
__device__ unsigned g_gen = 0;

// ------------------------- grid-wide barrier -------------------------------
__device__ __forceinline__ void gsync() {
    __syncthreads();
    if (threadIdx.x == 0) {
        __threadfence();
        unsigned g = *(volatile unsigned*)&g_gen;
        unsigned a = atomicAdd(&g_cnt, 1u);
        if (a == gridDim.x - 1u) {
            *(volatile unsigned*)&g_cnt = 0u;
            __threadfence();
            *(volatile unsigned*)&g_gen = g + 1u;
        } else {
            while (*(volatile unsigned*)&g_gen == g) { }
        }
        __threadfence();
    }
    __syncthreads();
}

__device__ __forceinline__ float wsum(float v) {
    #pragma unroll
    for (int o = 16; o > 0; o >>= 1) v += __shfl_xor_sync(0xffffffffu, v, o);
    return v;
}
__device__ __forceinline__ float sigm(float v) { return 1.f / (1.f + expf(-v)); }

// ------------------------- packed f32x2 helpers ----------------------------
__device__ __forceinline__ uint64_t bcast2(float f) {
    uint32_t u = __float_as_uint(f);
    uint64_t r;
    asm("mov.b64 %0, {%1,%1};" : "=l"(r) : "r"(u));
    return r;
}
__device__ __forceinline__ void fma2(uint64_t& d, uint64_t a, uint64_t b) {
    asm("fma.rn.f32x2 %0, %1, %2, %0;" : "+l"(d) : "l"(a), "l"(b));
}
__device__ __forceinline__ void lds_v2u64(uint64_t& x, uint64_t& y, const float* p) {
    uint32_t a = (uint32_t)__cvta_generic_to_shared(p);
    asm("ld.shared.v2.u64 {%0,%1}, [%2];" : "=l"(x), "=l"(y) : "r"(a));
}

// ------------------------- double-buffered SIMT GEMM ------------------------
// C(TM x 128) = A(TM x K) @ W(K x 128).  Per-thread tile: (TM/16) rows x 8 cols.
// A source: PTR ? rowptr[row]+k : (k<kBound ? A0[row*lda+k] : A1[row*lda+k-kBound])
template<int TM, bool PTR>
__device__ void gemm_tile(float* AsBuf, float* BsBuf, const float* const* rowptr,
    const float* __restrict__ A0, const float* __restrict__ A1, int lda, int kBound,
    const float* __restrict__ W0, const float* __restrict__ W1, int ldw,
    int kStart, int kCount, float* __restrict__ C, int ldc)
{
    constexpr int TN = 128;
    constexpr int RI = TM / 16;              // rows per thread
    const int tid = threadIdx.x;
    const int tx = tid & 15;                 // 16 col groups x 8
    const int ty = tid >> 4;                 // 16 row groups x RI
    const int am = tid >> 2;                 // A stage: row (0..63)
    const int ak = (tid & 3) << 2;           // A stage: 4 consecutive k
    const int wrow = tid >> 5;               // B stage: k row (0..7), 2 passes
    const int wcol = (tid & 31) << 2;        // B stage: 4 consecutive n

    uint64_t acc[RI][4];
    #pragma unroll
    for (int i = 0; i < RI; i++)
        #pragma unroll
        for (int j = 0; j < 4; j++) acc[i][j] = 0ull;

    auto stageA = [&](int buf, int kg) {
        #pragma unroll
        for (int r = 0; r < TM / 64; r++) {
            int row = am + r * 64;
            int k = kg + ak;
            const float* src;
            if (PTR) src = rowptr[row] + k;
            else     src = (k < kBound) ? (A0 + (size_t)row * lda + k)
                                        : (A1 + (size_t)row * lda + (k - kBound));
            float4 v = *(const float4*)src;
            float* d = AsBuf + buf * (16 * TM);
            d[(ak + 0) * TM + row] = v.x;
            d[(ak + 1) * TM + row] = v.y;
            d[(ak + 2) * TM + row] = v.z;
            d[(ak + 3) * TM + row] = v.w;
        }
    };
    auto stageB = [&](int buf, int kg) {
        #pragma unroll
        for (int r = 0; r < 2; r++) {
            int kr = wrow + r * 8;
            int k = kg + kr;
            const float* src = (k < kBound) ? (W0 + (size_t)k * ldw + wcol)
                                            : (W1 + (size_t)(k - kBound) * ldw + wcol);
            *(float4*)(BsBuf + buf * (16 * TN) + kr * TN + wcol) = *(const float4*)src;
        }
    };

    const int ntiles = kCount >> 4;
    stageA(0, kStart);
    stageB(0, kStart);
    __syncthreads();

    for (int t = 0; t < ntiles; t++) {
        const int cur = t & 1;
        if (t + 1 < ntiles) {
            stageA(cur ^ 1, kStart + (t + 1) * 16);
            stageB(cur ^ 1, kStart + (t + 1) * 16);
        }
        const float* Asb = AsBuf + cur * (16 * TM);
        const float* Bsb = BsBuf + cur * (16 * TN);
        #pragma unroll
        for (int k = 0; k < 16; k++) {
            uint64_t a[RI];
            #pragma unroll
            for (int g = 0; g < RI / 4; g++) {
                float4 af = *(const float4*)(Asb + k * TM + ty * RI + g * 4);
                a[g*4+0] = bcast2(af.x); a[g*4+1] = bcast2(af.y);
                a[g*4+2] = bcast2(af.z); a[g*4+3] = bcast2(af.w);
            }
            uint64_t b0, b1, b2, b3;
            lds_v2u64(b0, b1, Bsb + k * TN + tx * 8);
            lds_v2u64(b2, b3, Bsb + k * TN + tx * 8 + 4);
            #pragma unroll
            for (int i = 0; i < RI; i++) {
                fma2(acc[i][0], a[i], b0);
                fma2(acc[i][1], a[i], b1);
                fma2(acc[i][2], a[i], b2);
                fma2(acc[i][3], a[i], b3);
            }
        }
        __syncthreads();
    }

    #pragma unroll
    for (int i = 0; i < RI; i++) {
        float* dst = C + (size_t)(ty * RI + i) * ldc + tx * 8;
        ulonglong2 v0; v0.x = acc[i][0]; v0.y = acc[i][1];
        ulonglong2 v1; v1.x = acc[i][2]; v1.y = acc[i][3];
        *(ulonglong2*)(dst)     = v0;
        *(ulonglong2*)(dst + 4) = v1;
    }
}

// ------------------------- persistent kernel -------------------------------
__global__ void __launch_bounds__(NTHREADS, 2)
sqac_kernel(const float* __restrict__ question, const float* __restrict__ answer,
            const float* __restrict__ x, const int* __restrict__ ping,
            const float* __restrict__ h0, const float* __restrict__ c0,
            const float* __restrict__ Wqh, const float* __restrict__ bqh,
            const float* __restrict__ Wah, const float* __restrict__ bah,
            const float* __restrict__ Wih, const float* __restrict__ bih,
            const float* __restrict__ Whh, const float* __restrict__ bhh,
            const float* __restrict__ Wq,  const float* __restrict__ bq,
            const float* __restrict__ Wk,  const float* __restrict__ bk,
            const float* __restrict__ Wv,  const float* __restrict__ bv,
            const float* __restrict__ Wfuse, const float* __restrict__ bfuse,
            float* __restrict__ out)
{
    __shared__ float As[2 * 16 * 128];            // 16 KB
    __shared__ float Bs[2 * 16 * 128];            // 16 KB
    __shared__ const float* s_rowptr[128];        // QKV gathered-row pointers

    const int idx0   = blockIdx.x * blockDim.x + threadIdx.x;
    const int stride = gridDim.x * blockDim.x;
    const int bid    = blockIdx.x;
    const int nblk   = gridDim.x;
    const int tid    = threadIdx.x;

    // ---- prologue phase 1: state init + newv(0)=x[0] + base partials ----
    for (int idx = idx0; idx < B_ * H_; idx += stride) {
        g_h[idx] = h0[idx];
        g_c[idx] = c0[idx];
        g_newvAll[idx] = x[idx];                 // newv(0) = right (cond false at t=0)
    }
    for (int task = bid; task < 24 * SK_G; task += nblk) {
        int nt = task / SK_G, kc = task % SK_G;
        int n0 = nt * 128;
        gemm_tile<64, false>(As, Bs, nullptr, question, answer, H_, H_,
                             Wqh + n0, Wah + n0, G4H,
                             kc * 256, 256, g_gp + (size_t)kc * (B_ * G4H) + n0, G4H);
    }
    gsync();

    // ---- prologue phase 2: combine base + biases -------------------------
    for (int idx = idx0; idx < B_ * G4H; idx += stride) {
        int n = idx % G4H;
        float s = bqh[n] + bah[n] + bih[n] + bhh[n];
        #pragma unroll
        for (int kc = 0; kc < SK_G; kc++) s += g_gp[(size_t)kc * (B_ * G4H) + idx];
        g_base[idx] = s;
    }
    gsync();

    // =====================================================================
    for (int t = 0; t < T_; t++) {
        // ---- X: gates(t) GEMM  ||  QKV(t+1) GEMM (with inline gather) ----
        for (int task = bid; task < 288; task += nblk) {
            if (task < 144) {
                int nt = task / SK_G, kc = task % SK_G;   // 24 x 6
                int n0 = nt * 128;
                gemm_tile<64, false>(As, Bs, nullptr,
                    g_newvAll + (size_t)t * (B_ * H_), g_h, H_, H_,
                    Wih + n0, Whh + n0, G4H,
                    kc * 256, 256, g_gp + (size_t)kc * (B_ * G4H) + n0, G4H);
            } else if (t + 1 < T_) {
                int r = task - 144;
                int nt = r / SK_QKV, kc = r % SK_QKV;     // 18 x 8
                int n0 = nt * 128;
                int wsel = n0 / H_;
                int ncol = n0 - wsel * H_;
                const float* Wb = (wsel == 0) ? Wq : ((wsel == 1) ? Wk : Wv);
                // build gathered row pointers for step t+1
                if (tid < 128) {
                    int m = tid, b = m >> 1, s = m & 1;
                    const float* p;
                    if (s) {
                        p = x + ((size_t)(t + 1) * B_ + b) * H_;
                    } else {
                        int pt = ping[b * T_ + (t + 1)];
                        int i2 = pt - 1;
                        i2 = i2 < 0 ? 0 : (i2 > T_ - 1 ? T_ - 1 : i2);
                        p = ((i2 <= t) ? g_newvAll : x) + ((size_t)i2 * B_ + b) * H_;
                    }
                    s_rowptr[m] = p;
                }
                __syncthreads();
                gemm_tile<128, true>(As, Bs, s_rowptr,
                    nullptr, nullptr, 0, 1 << 28,
                    Wb + ncol, Wb + ncol, H_,
                    kc * 96, 96,
                    g_qkvp + (size_t)kc * (2 * B_ * QKVW) + n0, QKVW);
            }
        }
        gsync();

        // ---- Y: attention(t+1) on CTAs [0,96) || LSTM pointwise(t) on rest
        if (bid < 96) {
            if (t + 1 < T_) {
                int task = bid * (NTHREADS / 32) + (tid >> 5);   // exactly 768
                int lane = tid & 31;
                int b = task / NH_, h = task - b * NH_;
                float q[2][2], kk2[2][2], vv[2][2];
                #pragma unroll
                for (int s = 0; s < 2; s++) {
                    int row = (b * 2 + s) * QKVW;
                    #pragma unroll
                    for (int dd = 0; dd < 2; dd++) {
                        int d = lane + dd * 32;
                        int col = h * HD_ + d;
                        float qv = bq[col], kv = bk[col], vvv = bv[col];
                        #pragma unroll
                        for (int kc = 0; kc < SK_QKV; kc++) {
                            const float* p = g_qkvp + (size_t)kc * (2 * B_ * QKVW) + row;
                            qv  += p[col];
                            kv  += p[H_ + col];
                            vvv += p[2 * H_ + col];
                        }
                        q[s][dd] = qv; kk2[s][dd] = kv; vv[s][dd] = vvv;
                    }
                }
                float s00 = wsum(q[0][0]*kk2[0][0] + q[0][1]*kk2[0][1]) * 0.125f;
                float s01 = wsum(q[0][0]*kk2[1][0] + q[0][1]*kk2[1][1]) * 0.125f;
                float s10 = wsum(q[1][0]*kk2[0][0] + q[1][1]*kk2[0][1]) * 0.125f;
                float s11 = wsum(q[1][0]*kk2[1][0] + q[1][1]*kk2[1][1]) * 0.125f;
                float m0 = fmaxf(s00, s01), m1 = fmaxf(s10, s11);
                float e00 = expf(s00 - m0), e01 = expf(s01 - m0);
                float e10 = expf(s10 - m1), e11 = expf(s11 - m1);
                float r0 = 1.f / (e00 + e01), r1 = 1.f / (e10 + e11);
                float p00 = e00 * r0, p01 = e01 * r0, p10 = e10 * r1, p11 = e11 * r1;
                #pragma unroll
                for (int dd = 0; dd < 2; dd++) {
                    int d = lane + dd * 32;
                    g_ctx[b * (2*H_) + h * HD_ + d]      = p00 * vv[0][dd] + p01 * vv[1][dd];
                    g_ctx[b * (2*H_) + H_ + h * HD_ + d] = p10 * vv[0][dd] + p11 * vv[1][dd];
                }
            }
        } else {
            for (int idx = (bid - 96) * NTHREADS + tid; idx < B_ * H_;
                 idx += (nblk - 96) * NTHREADS) {
                int b = idx / H_, j = idx - b * H_;
                float gg[4];
                #pragma unroll
                for (int u = 0; u < 4; u++) {
                    int col = b * G4H + u * H_ + j;
                    float s = g_base[col];
                    #pragma unroll
                    for (int kc = 0; kc < SK_G; kc++) s += g_gp[(size_t)kc * (B_ * G4H) + col];
                    gg[u] = s;
                }
                float iv = sigm(gg[0]);
                float fv = sigm(gg[1]);
                float gv = tanhf(gg[2]);
                float ov = sigm(gg[3]);
                float c = fv * g_c[idx] + iv * gv;
                float h = ov * tanhf(c);
                g_c[idx] = c;
                g_h[idx] = h;
                out[((size_t)t * B_ + b) * H_ + j] = h;
                if (t == T_ - 1) {
                    out[((size_t)T_ * B_ + b) * H_ + j]       = h;   // hT
                    out[((size_t)(T_ + 1) * B_ + b) * H_ + j] = c;   // cT
                }
            }
        }
        gsync();

        if (t + 1 < T_) {
            // ---- Z: fuse(t+1) GEMM, C(64x768), K=1536 --------------------
            for (int task = bid; task < 6 * SK_F; task += nblk) {
                int nt = task / SK_F, kc = task % SK_F;    // 6 x 24
                int n0 = nt * 128;
                gemm_tile<64, false>(As, Bs, nullptr,
                    g_ctx, g_ctx, 2 * H_, 1 << 28,
                    Wfuse + n0, Wfuse + n0, H_,
                    kc * 64, 64, g_fp + (size_t)kc * (B_ * H_) + n0, H_);
            }
            gsync();

            // ---- W: combine fuse + select -> newv(t+1) -------------------
            for (int idx = idx0; idx < B_ * H_; idx += stride) {
                int b = idx / H_, j = idx - b * H_;
                float e = bfuse[j];
                #pragma unroll
                for (int kc = 0; kc < SK_F; kc++) e += g_fp[(size_t)kc * (B_ * H_) + idx];
                int pt = ping[b * T_ + (t + 1)];
                float right = x[((size_t)(t + 1) * B_ + b) * H_ + j];
                g_newvAll[(size_t)(t + 1) * (B_ * H_) + idx] = (pt > 0) ? e : right;
            }
            gsync();
        }
    }
}

// ------------------------- host launch --------------------------------------
extern "C" void kernel_launch(void* const* d_in, const int* in_sizes, int n_in,
                              void* d_out, int out_size)
{
    (void)in_sizes; (void)n_in; (void)out_size;
    const float* question = (const float*)d_in[0];
    const float* answer   = (const float*)d_in[1];
    const float* x        = (const float*)d_in[2];
    const int*   ping     = (const int*)  d_in[3];
    const float* h0       = (const float*)d_in[4];
    const float* c0       = (const float*)d_in[5];
    const float* Wqh      = (const float*)d_in[6];
    const float* bqh      = (const float*)d_in[7];
    const float* Wah      = (const float*)d_in[8];
    const float* bah      = (const float*)d_in[9];
    const float* Wih      = (const float*)d_in[10];
    const float* bih      = (const float*)d_in[11];
    const float* Whh      = (const float*)d_in[12];
    const float* bhh      = (const float*)d_in[13];
    const float* Wq       = (const float*)d_in[14];
    const float* bq       = (const float*)d_in[15];
    const float* Wk       = (const float*)d_in[16];
    const float* bk       = (const float*)d_in[17];
    const float* Wv       = (const float*)d_in[18];
    const float* bv       = (const float*)d_in[19];
    const float* Wfuse    = (const float*)d_in[20];
    const float* bfuse    = (const float*)d_in[21];

    int dev = 0;
    cudaGetDevice(&dev);
    int nsm = 148;
    cudaDeviceGetAttribute(&nsm, cudaDevAttrMultiProcessorCount, dev);
    int grid = nsm * 2;

    sqac_kernel<<<grid, NTHREADS>>>(question, answer, x, ping, h0, c0,
                                    Wqh, bqh, Wah, bah, Wih, bih, Whh, bhh,
                                    Wq, bq, Wk, bk, Wv, bv, Wfuse, bfuse,
                                    (float*)d_out);
}

// round 4
// speedup vs baseline: 1.6787x; 1.6787x over previous
#include <cuda_runtime.h>
#include <cuda_bf16.h>
#include <math.h>
#include <stdint.h>

#define T_  256
#define B_  64
#define H_  768
#define NH_ 12
#define HD_ 64
#define G4H 3072
#define QKVW 2304
#define NTHREADS 256

#define SK_G   6     // gates: 24 n-tiles(128) x 6  = 144 tasks, K=256
#define SK_QKV 4     // QKV:   36 tiles       x 4  = 144 tasks, K=192
#define SK_F   12    // fuse:   6 n-tiles(128) x 12 = 72 tasks,  K=128

// ------------------------- device scratch ----------------------------------
__device__ __align__(256) float g_newvAll[T_*B_*H_];
__device__ __align__(256) float g_qkvp[SK_QKV * 2*B_ * QKVW];
__device__ __align__(256) float g_ctx[B_*2*H_];
__device__ __align__(256) float g_fp[SK_F * B_ * H_];
__device__ __align__(256) float g_gp[SK_G * B_ * G4H];
__device__ __align__(256) float g_base[B_*G4H];
__device__ __align__(256) float g_h[B_*H_];
__device__ __align__(256) float g_c[B_*H_];
__device__ unsigned g_cnt = 0;
__device__ unsigned g_gen = 0;

// transposed split-bf16 weights: Wt[n][k]
__device__ __align__(256) __nv_bfloat16 WbaseT_hi[G4H*1536], WbaseT_lo[G4H*1536]; // [Wqh;Wah]
__device__ __align__(256) __nv_bfloat16 WgT_hi[G4H*1536],   WgT_lo[G4H*1536];     // [Wih;Whh]
__device__ __align__(256) __nv_bfloat16 WqkvT_hi[QKVW*H_],  WqkvT_lo[QKVW*H_];    // [Wq|Wk|Wv]
__device__ __align__(256) __nv_bfloat16 WfuseT_hi[H_*1536], WfuseT_lo[H_*1536];

// ------------------------- grid-wide barrier -------------------------------
__device__ __forceinline__ void gsync() {
    __syncthreads();
    if (threadIdx.x == 0) {
        __threadfence();
        unsigned g = *(volatile unsigned*)&g_gen;
        unsigned a = atomicAdd(&g_cnt, 1u);
        if (a == gridDim.x - 1u) {
            *(volatile unsigned*)&g_cnt = 0u;
            __threadfence();
            *(volatile unsigned*)&g_gen = g + 1u;
        } else {
            while (*(volatile unsigned*)&g_gen == g) { }
        }
        __threadfence();
    }
    __syncthreads();
}

__device__ __forceinline__ float wsum(float v) {
    #pragma unroll
    for (int o = 16; o > 0; o >>= 1) v += __shfl_xor_sync(0xffffffffu, v, o);
    return v;
}
__device__ __forceinline__ float sigm(float v) { return 1.f / (1.f + expf(-v)); }

__device__ __forceinline__ void bsplit(float v, __nv_bfloat16& h, __nv_bfloat16& l) {
    h = __float2bfloat16(v);
    l = __float2bfloat16(v - __bfloat162float(h));
}

// ------------------------- mma.sync wrapper --------------------------------
__device__ __forceinline__ void mma16816(float* c, const uint32_t* a, const uint32_t* b) {
    asm volatile(
        "mma.sync.aligned.m16n8k16.row.col.f32.bf16.bf16.f32 "
        "{%0,%1,%2,%3}, {%4,%5,%6,%7}, {%8,%9}, {%0,%1,%2,%3};"
        : "+f"(c[0]), "+f"(c[1]), "+f"(c[2]), "+f"(c[3])
        : "r"(a[0]), "r"(a[1]), "r"(a[2]), "r"(a[3]), "r"(b[0]), "r"(b[1]));
}
__device__ __forceinline__ uint32_t lds32(const __nv_bfloat16* p) {
    return *(const uint32_t*)p;
}

// ------------------------- split-bf16 MMA GEMM ------------------------------
// C(64 x 128) = A(64 x K) @ W(K x 128), fp32-precision via hi/lo bf16 3-pass.
// A fp32: PTR ? rowptr[row]+k : (k<kBound ? A0[row*lda+k] : A1[row*lda+(k-kBound)])
// W: transposed bf16 Wt[n][k], pre-offset to n0; row length Wld.
template<bool PTR>
__device__ void mma_gemm(__nv_bfloat16* sAh, __nv_bfloat16* sAl,
                         __nv_bfloat16* sBh, __nv_bfloat16* sBl,
                         const float* const* rowptr,
                         const float* __restrict__ A0, const float* __restrict__ A1,
                         int lda, int kBound,
                         const __nv_bfloat16* __restrict__ Wthi,
                         const __nv_bfloat16* __restrict__ Wtlo, int Wld,
                         int kStart, int kCount, float* __restrict__ C, int ldc)
{
    const int tid = threadIdx.x;
    const int w = tid >> 5, lane = tid & 31;
    const int g = lane >> 2, tg = lane & 3;
    const int mrow = (w >> 2) * 32;      // warp grid 2 (m) x 4 (n)
    const int ncol = (w & 3) * 32;

    // staging indices
    const int arow = tid >> 2, ak4 = (tid & 3) * 4;       // A: 64 rows x 16 k
    const int brow = tid & 127; const bool blo = tid >= 128;

    float acc[2][4][4];
    #pragma unroll
    for (int i = 0; i < 2; i++)
        #pragma unroll
        for (int j = 0; j < 4; j++)
            #pragma unroll
            for (int q = 0; q < 4; q++) acc[i][j][q] = 0.f;

    auto stageA = [&](int buf, int kg) {
        int k = kg + ak4;
        const float* src;
        if (PTR) src = rowptr[arow] + k;
        else     src = (k < kBound) ? (A0 + (size_t)arow * lda + k)
                                    : (A1 + (size_t)arow * lda + (k - kBound));
        float4 v = *(const float4*)src;
        __nv_bfloat16 h[4], l[4];
        bsplit(v.x, h[0], l[0]); bsplit(v.y, h[1], l[1]);
        bsplit(v.z, h[2], l[2]); bsplit(v.w, h[3], l[3]);
        *(uint64_t*)(sAh + (size_t)buf * 1024 + arow * 16 + ak4) = *(uint64_t*)h;
        *(uint64_t*)(sAl + (size_t)buf * 1024 + arow * 16 + ak4) = *(uint64_t*)l;
    };
    auto stageB = [&](int buf, int kg) {
        const __nv_bfloat16* src = (blo ? Wtlo : Wthi) + (size_t)brow * Wld + kg;
        __nv_bfloat16* dst = (blo ? sBl : sBh) + (size_t)buf * 2048 + brow * 16;
        uint4 v0 = *(const uint4*)src;
        uint4 v1 = *(const uint4*)(src + 8);
        *(uint4*)dst = v0;
        *(uint4*)(dst + 8) = v1;
    };

    const int nkt = kCount >> 4;
    stageA(0, kStart);
    stageB(0, kStart);
    __syncthreads();

    for (int t = 0; t < nkt; t++) {
        const int cur = t & 1;
        if (t + 1 < nkt) {
            stageA(cur ^ 1, kStart + (t + 1) * 16);
            stageB(cur ^ 1, kStart + (t + 1) * 16);
        }
        const __nv_bfloat16* Ah = sAh + (size_t)cur * 1024;
        const __nv_bfloat16* Al = sAl + (size_t)cur * 1024;
        const __nv_bfloat16* Bh = sBh + (size_t)cur * 2048;
        const __nv_bfloat16* Bl = sBl + (size_t)cur * 2048;

        uint32_t ahf[2][4], alf[2][4], bhf[4][2], blf[4][2];
        #pragma unroll
        for (int mt = 0; mt < 2; mt++) {
            int r0 = mrow + mt * 16;
            ahf[mt][0] = lds32(Ah + (r0 + g) * 16 + 2 * tg);
            ahf[mt][1] = lds32(Ah + (r0 + g + 8) * 16 + 2 * tg);
            ahf[mt][2] = lds32(Ah + (r0 + g) * 16 + 2 * tg + 8);
            ahf[mt][3] = lds32(Ah + (r0 + g + 8) * 16 + 2 * tg + 8);
            alf[mt][0] = lds32(Al + (r0 + g) * 16 + 2 * tg);
            alf[mt][1] = lds32(Al + (r0 + g + 8) * 16 + 2 * tg);
            alf[mt][2] = lds32(Al + (r0 + g) * 16 + 2 * tg + 8);
            alf[mt][3] = lds32(Al + (r0 + g + 8) * 16 + 2 * tg + 8);
        }
        #pragma unroll
        for (int nt = 0; nt < 4; nt++) {
            int n0 = ncol + nt * 8;
            bhf[nt][0] = lds32(Bh + (n0 + g) * 16 + 2 * tg);
            bhf[nt][1] = lds32(Bh + (n0 + g) * 16 + 2 * tg + 8);
            blf[nt][0] = lds32(Bl + (n0 + g) * 16 + 2 * tg);
            blf[nt][1] = lds32(Bl + (n0 + g) * 16 + 2 * tg + 8);
        }
        #pragma unroll
        for (int mt = 0; mt < 2; mt++)
            #pragma unroll
            for (int nt = 0; nt < 4; nt++) {
                mma16816(acc[mt][nt], ahf[mt], bhf[nt]);   // hi*hi
                mma16816(acc[mt][nt], ahf[mt], blf[nt]);   // hi*lo
                mma16816(acc[mt][nt], alf[mt], bhf[nt]);   // lo*hi
            }
        __syncthreads();
    }

    #pragma unroll
    for (int mt = 0; mt < 2; mt++)
        #pragma unroll
        for (int nt = 0; nt < 4; nt++) {
            float* dst0 = C + (size_t)(mrow + mt * 16 + g) * ldc + ncol + nt * 8 + 2 * tg;
            float* dst1 = dst0 + 8 * ldc;
            *(float2*)dst0 = make_float2(acc[mt][nt][0], acc[mt][nt][1]);
            *(float2*)dst1 = make_float2(acc[mt][nt][2], acc[mt][nt][3]);
        }
}

// ------------------------- weight prep kernel -------------------------------
__global__ void prep_kernel(const float* __restrict__ Wqh, const float* __restrict__ Wah,
                            const float* __restrict__ Wih, const float* __restrict__ Whh,
                            const float* __restrict__ Wq,  const float* __restrict__ Wk,
                            const float* __restrict__ Wv,  const float* __restrict__ Wfuse)
{
    const int idx0 = blockIdx.x * blockDim.x + threadIdx.x;
    const int stride = gridDim.x * blockDim.x;
    // WbaseT / WgT: [n=3072][k=1536]
    for (int i = idx0; i < G4H * 1536; i += stride) {
        int n = i / 1536, k = i % 1536;
        float vb = (k < H_) ? Wqh[(size_t)k * G4H + n] : Wah[(size_t)(k - H_) * G4H + n];
        float vg = (k < H_) ? Wih[(size_t)k * G4H + n] : Whh[(size_t)(k - H_) * G4H + n];
        __nv_bfloat16 h, l;
        bsplit(vb, h, l); WbaseT_hi[i] = h; WbaseT_lo[i] = l;
        bsplit(vg, h, l); WgT_hi[i]   = h; WgT_lo[i]   = l;
    }
    // WqkvT: [n=2304][k=768]
    for (int i = idx0; i < QKVW * H_; i += stride) {
        int n = i / H_, k = i % H_;
        int ws = n / H_, nc = n - ws * H_;
        const float* W = (ws == 0) ? Wq : ((ws == 1) ? Wk : Wv);
        __nv_bfloat16 h, l;
        bsplit(W[(size_t)k * H_ + nc], h, l);
        WqkvT_hi[i] = h; WqkvT_lo[i] = l;
    }
    // WfuseT: [n=768][k=1536]
    for (int i = idx0; i < H_ * 1536; i += stride) {
        int n = i / 1536, k = i % 1536;
        __nv_bfloat16 h, l;
        bsplit(Wfuse[(size_t)k * H_ + n], h, l);
        WfuseT_hi[i] = h; WfuseT_lo[i] = l;
    }
}

// ------------------------- persistent kernel -------------------------------
__global__ void __launch_bounds__(NTHREADS, 2)
sqac_kernel(const float* __restrict__ question, const float* __restrict__ answer,
            const float* __restrict__ x, const int* __restrict__ ping,
            const float* __restrict__ h0, const float* __restrict__ c0,
            const float* __restrict__ bqh, const float* __restrict__ bah,
            const float* __restrict__ bih, const float* __restrict__ bhh,
            const float* __restrict__ bq,  const float* __restrict__ bk,
            const float* __restrict__ bv,  const float* __restrict__ bfuse,
            float* __restrict__ out)
{
    __shared__ __align__(16) __nv_bfloat16 sAh[2 * 1024];
    __shared__ __align__(16) __nv_bfloat16 sAl[2 * 1024];
    __shared__ __align__(16) __nv_bfloat16 sBh[2 * 2048];
    __shared__ __align__(16) __nv_bfloat16 sBl[2 * 2048];
    __shared__ const float* s_rowptr[64];

    const int idx0   = blockIdx.x * blockDim.x + threadIdx.x;
    const int stride = gridDim.x * blockDim.x;
    const int bid    = blockIdx.x;
    const int nblk   = gridDim.x;
    const int tid    = threadIdx.x;

    // ---- prologue 1: state init + newv(0)=x[0] + base GEMM ----------------
    for (int idx = idx0; idx < B_ * H_; idx += stride) {
        g_h[idx] = h0[idx];
        g_c[idx] = c0[idx];
        g_newvAll[idx] = x[idx];
    }
    for (int task = bid; task < 24 * SK_G; task += nblk) {
        int nt = task / SK_G, kc = task % SK_G;
        int n0 = nt * 128;
        mma_gemm<false>(sAh, sAl, sBh, sBl, nullptr,
                        question, answer, H_, H_,
                        WbaseT_hi + (size_t)n0 * 1536, WbaseT_lo + (size_t)n0 * 1536, 1536,
                        kc * 256, 256, g_gp + (size_t)kc * (B_ * G4H) + n0, G4H);
    }
    gsync();

    // ---- prologue 2: combine base + biases ---------------------------------
    for (int idx = idx0; idx < B_ * G4H; idx += stride) {
        int n = idx % G4H;
        float s = bqh[n] + bah[n] + bih[n] + bhh[n];
        #pragma unroll
        for (int kc = 0; kc < SK_G; kc++) s += g_gp[(size_t)kc * (B_ * G4H) + idx];
        g_base[idx] = s;
    }
    gsync();

    // ========================================================================
    for (int t = 0; t < T_; t++) {
        // ---- X: gates(t) || QKV(t+1) ---------------------------------------
        for (int task = bid; task < 288; task += nblk) {
            if (task < 144) {
                int nt = task / SK_G, kc = task % SK_G;     // 24 x 6
                int n0 = nt * 128;
                mma_gemm<false>(sAh, sAl, sBh, sBl, nullptr,
                    g_newvAll + (size_t)t * (B_ * H_), g_h, H_, H_,
                    WgT_hi + (size_t)n0 * 1536, WgT_lo + (size_t)n0 * 1536, 1536,
                    kc * 256, 256, g_gp + (size_t)kc * (B_ * G4H) + n0, G4H);
            } else if (t + 1 < T_) {
                int r = task - 144;
                int tile = r >> 2, kc = r & 3;               // 36 x 4
                int mh = tile / 18, nt = tile % 18;
                int n0 = nt * 128;
                if (tid < 64) {
                    int m = mh * 64 + tid, b = m >> 1, s = m & 1;
                    const float* p;
                    if (s) {
                        p = x + ((size_t)(t + 1) * B_ + b) * H_;
                    } else {
                        int pt = ping[b * T_ + (t + 1)];
                        int i2 = pt - 1;
                        i2 = i2 < 0 ? 0 : (i2 > T_ - 1 ? T_ - 1 : i2);
                        p = ((i2 <= t) ? g_newvAll : x) + ((size_t)i2 * B_ + b) * H_;
                    }
                    s_rowptr[tid] = p;
                }
                __syncthreads();
                mma_gemm<true>(sAh, sAl, sBh, sBl, s_rowptr,
                    nullptr, nullptr, 0, 1 << 28,
                    WqkvT_hi + (size_t)n0 * H_, WqkvT_lo + (size_t)n0 * H_, H_,
                    kc * 192, 192,
                    g_qkvp + (size_t)kc * (128 * QKVW) + (size_t)(mh * 64) * QKVW + n0, QKVW);
            }
        }
        gsync();

        // ---- Y: attention(t+1) + LSTM(t) ------------------------------------
        if (t + 1 < T_) {
            int wid = bid * (NTHREADS / 32) + (tid >> 5);
            int lane = tid & 31;
            for (int task = wid; task < B_ * NH_; task += nblk * (NTHREADS / 32)) {
                int b = task / NH_, h = task - b * NH_;
                float q[2][2], kk2[2][2], vv[2][2];
                #pragma unroll
                for (int s = 0; s < 2; s++) {
                    int row = (b * 2 + s) * QKVW;
                    #pragma unroll
                    for (int dd = 0; dd < 2; dd++) {
                        int d = lane + dd * 32;
                        int col = h * HD_ + d;
                        float qv = bq[col], kv = bk[col], vvv = bv[col];
                        #pragma unroll
                        for (int kc = 0; kc < SK_QKV; kc++) {
                            const float* p = g_qkvp + (size_t)kc * (128 * QKVW) + row;
                            qv  += p[col];
                            kv  += p[H_ + col];
                            vvv += p[2 * H_ + col];
                        }
                        q[s][dd] = qv; kk2[s][dd] = kv; vv[s][dd] = vvv;
                    }
                }
                float s00 = wsum(q[0][0]*kk2[0][0] + q[0][1]*kk2[0][1]) * 0.125f;
                float s01 = wsum(q[0][0]*kk2[1][0] + q[0][1]*kk2[1][1]) * 0.125f;
                float s10 = wsum(q[1][0]*kk2[0][0] + q[1][1]*kk2[0][1]) * 0.125f;
                float s11 = wsum(q[1][0]*kk2[1][0] + q[1][1]*kk2[1][1]) * 0.125f;
                float m0 = fmaxf(s00, s01), m1 = fmaxf(s10, s11);
                float e00 = expf(s00 - m0), e01 = expf(s01 - m0);
                float e10 = expf(s10 - m1), e11 = expf(s11 - m1);
                float r0 = 1.f / (e00 + e01), r1 = 1.f / (e10 + e11);
                float p00 = e00 * r0, p01 = e01 * r0, p10 = e10 * r1, p11 = e11 * r1;
                #pragma unroll
                for (int dd = 0; dd < 2; dd++) {
                    int d = lane + dd * 32;
                    g_ctx[b * (2*H_) + h * HD_ + d]      = p00 * vv[0][dd] + p01 * vv[1][dd];
                    g_ctx[b * (2*H_) + H_ + h * HD_ + d] = p10 * vv[0][dd] + p11 * vv[1][dd];
                }
            }
        }
        for (int idx = idx0; idx < B_ * H_; idx += stride) {
            int b = idx / H_, j = idx - b * H_;
            float gg[4];
            #pragma unroll
            for (int u = 0; u < 4; u++) {
                int col = b * G4H + u * H_ + j;
                float s = g_base[col];
                #pragma unroll
                for (int kc = 0; kc < SK_G; kc++) s += g_gp[(size_t)kc * (B_ * G4H) + col];
                gg[u] = s;
            }
            float iv = sigm(gg[0]);
            float fv = sigm(gg[1]);
            float gv = tanhf(gg[2]);
            float ov = sigm(gg[3]);
            float c = fv * g_c[idx] + iv * gv;
            float h = ov * tanhf(c);
            g_c[idx] = c;
            g_h[idx] = h;
            out[((size_t)t * B_ + b) * H_ + j] = h;
            if (t == T_ - 1) {
                out[((size_t)T_ * B_ + b) * H_ + j]       = h;   // hT
                out[((size_t)(T_ + 1) * B_ + b) * H_ + j] = c;   // cT
            }
        }
        gsync();

        if (t + 1 < T_) {
            // ---- Z: fuse(t+1), C(64x768), K=1536, splitK 12 -----------------
            for (int task = bid; task < 6 * SK_F; task += nblk) {
                int nt = task / SK_F, kc = task % SK_F;
                int n0 = nt * 128;
                mma_gemm<false>(sAh, sAl, sBh, sBl, nullptr,
                    g_ctx, g_ctx, 2 * H_, 1 << 28,
                    WfuseT_hi + (size_t)n0 * 1536, WfuseT_lo + (size_t)n0 * 1536, 1536,
                    kc * 128, 128, g_fp + (size_t)kc * (B_ * H_) + n0, H_);
            }
            gsync();

            // ---- W: combine fuse + select -> newv(t+1) ----------------------
            for (int idx = idx0; idx < B_ * H_; idx += stride) {
                int b = idx / H_, j = idx - b * H_;
                float e = bfuse[j];
                #pragma unroll
                for (int kc = 0; kc < SK_F; kc++) e += g_fp[(size_t)kc * (B_ * H_) + idx];
                int pt = ping[b * T_ + (t + 1)];
                float right = x[((size_t)(t + 1) * B_ + b) * H_ + j];
                g_newvAll[(size_t)(t + 1) * (B_ * H_) + idx] = (pt > 0) ? e : right;
            }
            gsync();
        }
    }
}

// ------------------------- host launch --------------------------------------
extern "C" void kernel_launch(void* const* d_in, const int* in_sizes, int n_in,
                              void* d_out, int out_size)
{
    (void)in_sizes; (void)n_in; (void)out_size;
    const float* question = (const float*)d_in[0];
    const float* answer   = (const float*)d_in[1];
    const float* x        = (const float*)d_in[2];
    const int*   ping     = (const int*)  d_in[3];
    const float* h0       = (const float*)d_in[4];
    const float* c0       = (const float*)d_in[5];
    const float* Wqh      = (const float*)d_in[6];
    const float* bqh      = (const float*)d_in[7];
    const float* Wah      = (const float*)d_in[8];
    const float* bah      = (const float*)d_in[9];
    const float* Wih      = (const float*)d_in[10];
    const float* bih      = (const float*)d_in[11];
    const float* Whh      = (const float*)d_in[12];
    const float* bhh      = (const float*)d_in[13];
    const float* Wq       = (const float*)d_in[14];
    const float* bq       = (const float*)d_in[15];
    const float* Wk       = (const float*)d_in[16];
    const float* bk       = (const float*)d_in[17];
    const float* Wv       = (const float*)d_in[18];
    const float* bv       = (const float*)d_in[19];
    const float* Wfuse    = (const float*)d_in[20];
    const float* bfuse    = (const float*)d_in[21];

    int dev = 0;
    cudaGetDevice(&dev);
    int nsm = 148;
    cudaDeviceGetAttribute(&nsm, cudaDevAttrMultiProcessorCount, dev);

    prep_kernel<<<nsm * 8, 256>>>(Wqh, Wah, Wih, Whh, Wq, Wk, Wv, Wfuse);

    sqac_kernel<<<nsm * 2, NTHREADS>>>(question, answer, x, ping, h0, c0,
                                       bqh, bah, bih, bhh,
                                       bq, bk, bv, bfuse,
                                       (float*)d_out);
}

// round 5
// speedup vs baseline: 1.6952x; 1.0099x over previous
#include <cuda_runtime.h>
#include <cuda_bf16.h>
#include <math.h>
#include <stdint.h>

#define T_  256
#define B_  64
#define H_  768
#define NH_ 12
#define HD_ 64
#define G4H 3072
#define QKVW 2304
#define NTHREADS 256

#define SK_G   6     // gates: 24 n-tiles(128) x 6  = 144 tasks, K=256
#define SK_QKV 4     // QKV:   36 tiles       x 4  = 144 tasks, K=192
#define SK_F   12    // fuse:   6 n-tiles(128) x 12 = 72 tasks,  K=128

// ------------------------- device scratch ----------------------------------
__device__ __align__(256) float g_newvAll[T_*B_*H_];
__device__ __align__(256) float g_qkvp[SK_QKV * 2*B_ * QKVW];
__device__ __align__(256) float g_ctx[B_*2*H_];
__device__ __align__(256) float g_fp[SK_F * B_ * H_];
__device__ __align__(256) float g_gp[SK_G * B_ * G4H];
__device__ __align__(256) float g_base[B_*G4H];
__device__ __align__(256) float g_h[B_*H_];
__device__ __align__(256) float g_c[B_*H_];
__device__ unsigned g_cnt = 0;
__device__ unsigned g_gen = 0;

// transposed split-bf16 weights: Wt[n][k]
__device__ __align__(256) __nv_bfloat16 WbaseT_hi[G4H*1536], WbaseT_lo[G4H*1536]; // [Wqh;Wah]
__device__ __align__(256) __nv_bfloat16 WgT_hi[G4H*1536],   WgT_lo[G4H*1536];     // [Wih;Whh]
__device__ __align__(256) __nv_bfloat16 WqkvT_hi[QKVW*H_],  WqkvT_lo[QKVW*H_];    // [Wq|Wk|Wv]
__device__ __align__(256) __nv_bfloat16 WfuseT_hi[H_*1536], WfuseT_lo[H_*1536];

// ------------------------- grid-wide barrier -------------------------------
__device__ __forceinline__ void gsync() {
    __syncthreads();
    if (threadIdx.x == 0) {
        __threadfence();
        unsigned g = *(volatile unsigned*)&g_gen;
        unsigned a = atomicAdd(&g_cnt, 1u);
        if (a == gridDim.x - 1u) {
            *(volatile unsigned*)&g_cnt = 0u;
            __threadfence();
            *(volatile unsigned*)&g_gen = g + 1u;
        } else {
            while (*(volatile unsigned*)&g_gen == g) { }
        }
        __threadfence();
    }
    __syncthreads();
}

__device__ __forceinline__ float wsum(float v) {
    #pragma unroll
    for (int o = 16; o > 0; o >>= 1) v += __shfl_xor_sync(0xffffffffu, v, o);
    return v;
}
__device__ __forceinline__ float sigm(float v) { return 1.f / (1.f + expf(-v)); }

__device__ __forceinline__ void bsplit(float v, __nv_bfloat16& h, __nv_bfloat16& l) {
    h = __float2bfloat16(v);
    l = __float2bfloat16(v - __bfloat162float(h));
}

// ------------------------- mma.sync wrapper --------------------------------
__device__ __forceinline__ void mma16816(float* c, const uint32_t* a, const uint32_t* b) {
    asm volatile(
        "mma.sync.aligned.m16n8k16.row.col.f32.bf16.bf16.f32 "
        "{%0,%1,%2,%3}, {%4,%5,%6,%7}, {%8,%9}, {%0,%1,%2,%3};"
        : "+f"(c[0]), "+f"(c[1]), "+f"(c[2]), "+f"(c[3])
        : "r"(a[0]), "r"(a[1]), "r"(a[2]), "r"(a[3]), "r"(b[0]), "r"(b[1]));
}
__device__ __forceinline__ uint32_t lds32(const __nv_bfloat16* p) {
    return *(const uint32_t*)p;
}

// ------------------------- split-bf16 MMA GEMM ------------------------------
// C(64 x 128) = A(64 x K) @ W(K x 128), fp32-precision via hi/lo bf16 3-pass.
// A fp32: PTR ? rowptr[row]+k : (k<kBound ? A0[row*lda+k] : A1[row*lda+(k-kBound)])
// W: transposed bf16 Wt[n][k], pre-offset to n0; row length Wld.
template<bool PTR>
__device__ void mma_gemm(__nv_bfloat16* sAh, __nv_bfloat16* sAl,
                         __nv_bfloat16* sBh, __nv_bfloat16* sBl,
                         const float* const* rowptr,
                         const float* __restrict__ A0, const float* __restrict__ A1,
                         int lda, int kBound,
                         const __nv_bfloat16* __restrict__ Wthi,
                         const __nv_bfloat16* __restrict__ Wtlo, int Wld,
                         int kStart, int kCount, float* __restrict__ C, int ldc)
{
    const int tid = threadIdx.x;
    const int w = tid >> 5, lane = tid & 31;
    const int g = lane >> 2, tg = lane & 3;
    const int mrow = (w >> 2) * 32;      // warp grid 2 (m) x 4 (n)
    const int ncol = (w & 3) * 32;

    // staging indices
    const int arow = tid >> 2, ak4 = (tid & 3) * 4;       // A: 64 rows x 16 k
    const int brow = tid & 127; const bool blo = tid >= 128;

    float acc[2][4][4];
    #pragma unroll
    for (int i = 0; i < 2; i++)
        #pragma unroll
        for (int j = 0; j < 4; j++)
            #pragma unroll
            for (int q = 0; q < 4; q++) acc[i][j][q] = 0.f;

    auto stageA = [&](int buf, int kg) {
        int k = kg + ak4;
        const float* src;
        if (PTR) src = rowptr[arow] + k;
        else     src = (k < kBound) ? (A0 + (size_t)arow * lda + k)
                                    : (A1 + (size_t)arow * lda + (k - kBound));
        float4 v = *(const float4*)src;
        __nv_bfloat16 h[4], l[4];
        bsplit(v.x, h[0], l[0]); bsplit(v.y, h[1], l[1]);
        bsplit(v.z, h[2], l[2]); bsplit(v.w, h[3], l[3]);
        *(uint64_t*)(sAh + (size_t)buf * 1024 + arow * 16 + ak4) = *(uint64_t*)h;
        *(uint64_t*)(sAl + (size_t)buf * 1024 + arow * 16 + ak4) = *(uint64_t*)l;
    };
    auto stageB = [&](int buf, int kg) {
        const __nv_bfloat16* src = (blo ? Wtlo : Wthi) + (size_t)brow * Wld + kg;
        __nv_bfloat16* dst = (blo ? sBl : sBh) + (size_t)buf * 2048 + brow * 16;
        uint4 v0 = *(const uint4*)src;
        uint4 v1 = *(const uint4*)(src + 8);
        *(uint4*)dst = v0;
        *(uint4*)(dst + 8) = v1;
    };

    const int nkt = kCount >> 4;
    stageA(0, kStart);
    stageB(0, kStart);
    __syncthreads();

    for (int t = 0; t < nkt; t++) {
        const int cur = t & 1;
        if (t + 1 < nkt) {
            stageA(cur ^ 1, kStart + (t + 1) * 16);
            stageB(cur ^ 1, kStart + (t + 1) * 16);
        }
        const __nv_bfloat16* Ah = sAh + (size_t)cur * 1024;
        const __nv_bfloat16* Al = sAl + (size_t)cur * 1024;
        const __nv_bfloat16* Bh = sBh + (size_t)cur * 2048;
        const __nv_bfloat16* Bl = sBl + (size_t)cur * 2048;

        uint32_t ahf[2][4], alf[2][4], bhf[4][2], blf[4][2];
        #pragma unroll
        for (int mt = 0; mt < 2; mt++) {
            int r0 = mrow + mt * 16;
            ahf[mt][0] = lds32(Ah + (r0 + g) * 16 + 2 * tg);
            ahf[mt][1] = lds32(Ah + (r0 + g + 8) * 16 + 2 * tg);
            ahf[mt][2] = lds32(Ah + (r0 + g) * 16 + 2 * tg + 8);
            ahf[mt][3] = lds32(Ah + (r0 + g + 8) * 16 + 2 * tg + 8);
            alf[mt][0] = lds32(Al + (r0 + g) * 16 + 2 * tg);
            alf[mt][1] = lds32(Al + (r0 + g + 8) * 16 + 2 * tg);
            alf[mt][2] = lds32(Al + (r0 + g) * 16 + 2 * tg + 8);
            alf[mt][3] = lds32(Al + (r0 + g + 8) * 16 + 2 * tg + 8);
        }
        #pragma unroll
        for (int nt = 0; nt < 4; nt++) {
            int n0 = ncol + nt * 8;
            bhf[nt][0] = lds32(Bh + (n0 + g) * 16 + 2 * tg);
            bhf[nt][1] = lds32(Bh + (n0 + g) * 16 + 2 * tg + 8);
            blf[nt][0] = lds32(Bl + (n0 + g) * 16 + 2 * tg);
            blf[nt][1] = lds32(Bl + (n0 + g) * 16 + 2 * tg + 8);
        }
        #pragma unroll
        for (int mt = 0; mt < 2; mt++)
            #pragma unroll
            for (int nt = 0; nt < 4; nt++) {
                mma16816(acc[mt][nt], ahf[mt], bhf[nt]);   // hi*hi
                mma16816(acc[mt][nt], ahf[mt], blf[nt]);   // hi*lo
                mma16816(acc[mt][nt], alf[mt], bhf[nt]);   // lo*hi
            }
        __syncthreads();
    }

    #pragma unroll
    for (int mt = 0; mt < 2; mt++)
        #pragma unroll
        for (int nt = 0; nt < 4; nt++) {
            float* dst0 = C + (size_t)(mrow + mt * 16 + g) * ldc + ncol + nt * 8 + 2 * tg;
            float* dst1 = dst0 + 8 * ldc;
            *(float2*)dst0 = make_float2(acc[mt][nt][0], acc[mt][nt][1]);
            *(float2*)dst1 = make_float2(acc[mt][nt][2], acc[mt][nt][3]);
        }
}

// ------------------------- weight prep kernel -------------------------------
__global__ void prep_kernel(const float* __restrict__ Wqh, const float* __restrict__ Wah,
                            const float* __restrict__ Wih, const float* __restrict__ Whh,
                            const float* __restrict__ Wq,  const float* __restrict__ Wk,
                            const float* __restrict__ Wv,  const float* __restrict__ Wfuse)
{
    const int idx0 = blockIdx.x * blockDim.x + threadIdx.x;
    const int stride = gridDim.x * blockDim.x;
    // WbaseT / WgT: [n=3072][k=1536]
    for (int i = idx0; i < G4H * 1536; i += stride) {
        int n = i / 1536, k = i % 1536;
        float vb = (k < H_) ? Wqh[(size_t)k * G4H + n] : Wah[(size_t)(k - H_) * G4H + n];
        float vg = (k < H_) ? Wih[(size_t)k * G4H + n] : Whh[(size_t)(k - H_) * G4H + n];
        __nv_bfloat16 h, l;
        bsplit(vb, h, l); WbaseT_hi[i] = h; WbaseT_lo[i] = l;
        bsplit(vg, h, l); WgT_hi[i]   = h; WgT_lo[i]   = l;
    }
    // WqkvT: [n=2304][k=768]
    for (int i = idx0; i < QKVW * H_; i += stride) {
        int n = i / H_, k = i % H_;
        int ws = n / H_, nc = n - ws * H_;
        const float* W = (ws == 0) ? Wq : ((ws == 1) ? Wk : Wv);
        __nv_bfloat16 h, l;
        bsplit(W[(size_t)k * H_ + nc], h, l);
        WqkvT_hi[i] = h; WqkvT_lo[i] = l;
    }
    // WfuseT: [n=768][k=1536]
    for (int i = idx0; i < H_ * 1536; i += stride) {
        int n = i / 1536, k = i % 1536;
        __nv_bfloat16 h, l;
        bsplit(Wfuse[(size_t)k * H_ + n], h, l);
        WfuseT_hi[i] = h; WfuseT_lo[i] = l;
    }
}

// ------------------------- persistent kernel -------------------------------
__global__ void __launch_bounds__(NTHREADS, 2)
sqac_kernel(const float* __restrict__ question, const float* __restrict__ answer,
            const float* __restrict__ x, const int* __restrict__ ping,
            const float* __restrict__ h0, const float* __restrict__ c0,
            const float* __restrict__ bqh, const float* __restrict__ bah,
            const float* __restrict__ bih, const float* __restrict__ bhh,
            const float* __restrict__ bq,  const float* __restrict__ bk,
            const float* __restrict__ bv,  const float* __restrict__ bfuse,
            float* __restrict__ out)
{
    __shared__ __align__(16) __nv_bfloat16 sAh[2 * 1024];
    __shared__ __align__(16) __nv_bfloat16 sAl[2 * 1024];
    __shared__ __align__(16) __nv_bfloat16 sBh[2 * 2048];
    __shared__ __align__(16) __nv_bfloat16 sBl[2 * 2048];
    __shared__ const float* s_rowptr[64];

    const int idx0   = blockIdx.x * blockDim.x + threadIdx.x;
    const int stride = gridDim.x * blockDim.x;
    const int bid    = blockIdx.x;
    const int nblk   = gridDim.x;
    const int tid    = threadIdx.x;

    // ---- prologue 1: state init + newv(0)=x[0] + base GEMM ----------------
    for (int idx = idx0; idx < B_ * H_; idx += stride) {
        g_h[idx] = h0[idx];
        g_c[idx] = c0[idx];
        g_newvAll[idx] = x[idx];
    }
    for (int task = bid; task < 24 * SK_G; task += nblk) {
        int nt = task / SK_G, kc = task % SK_G;
        int n0 = nt * 128;
        mma_gemm<false>(sAh, sAl, sBh, sBl, nullptr,
                        question, answer, H_, H_,
                        WbaseT_hi + (size_t)n0 * 1536, WbaseT_lo + (size_t)n0 * 1536, 1536,
                        kc * 256, 256, g_gp + (size_t)kc * (B_ * G4H) + n0, G4H);
    }
    gsync();

    // ---- prologue 2: combine base + biases ---------------------------------
    for (int idx = idx0; idx < B_ * G4H; idx += stride) {
        int n = idx % G4H;
        float s = bqh[n] + bah[n] + bih[n] + bhh[n];
        #pragma unroll
        for (int kc = 0; kc < SK_G; kc++) s += g_gp[(size_t)kc * (B_ * G4H) + idx];
        g_base[idx] = s;
    }
    gsync();

    // ========================================================================
    for (int t = 0; t < T_; t++) {
        // ---- X: gates(t) || QKV(t+1) ---------------------------------------
        for (int task = bid; task < 288; task += nblk) {
            if (task < 144) {
                int nt = task / SK_G, kc = task % SK_G;     // 24 x 6
                int n0 = nt * 128;
                mma_gemm<false>(sAh, sAl, sBh, sBl, nullptr,
                    g_newvAll + (size_t)t * (B_ * H_), g_h, H_, H_,
                    WgT_hi + (size_t)n0 * 1536, WgT_lo + (size_t)n0 * 1536, 1536,
                    kc * 256, 256, g_gp + (size_t)kc * (B_ * G4H) + n0, G4H);
            } else if (t + 1 < T_) {
                int r = task - 144;
                int tile = r >> 2, kc = r & 3;               // 36 x 4
                int mh = tile / 18, nt = tile % 18;
                int n0 = nt * 128;
                if (tid < 64) {
                    int m = mh * 64 + tid, b = m >> 1, s = m & 1;
                    const float* p;
                    if (s) {
                        p = x + ((size_t)(t + 1) * B_ + b) * H_;
                    } else {
                        int pt = ping[b * T_ + (t + 1)];
                        int i2 = pt - 1;
                        i2 = i2 < 0 ? 0 : (i2 > T_ - 1 ? T_ - 1 : i2);
                        p = ((i2 <= t) ? g_newvAll : x) + ((size_t)i2 * B_ + b) * H_;
                    }
                    s_rowptr[tid] = p;
                }
                __syncthreads();
                mma_gemm<true>(sAh, sAl, sBh, sBl, s_rowptr,
                    nullptr, nullptr, 0, 1 << 28,
                    WqkvT_hi + (size_t)n0 * H_, WqkvT_lo + (size_t)n0 * H_, H_,
                    kc * 192, 192,
                    g_qkvp + (size_t)kc * (128 * QKVW) + (size_t)(mh * 64) * QKVW + n0, QKVW);
            }
        }
        gsync();

        // ---- Y: attention(t+1) + LSTM(t) ------------------------------------
        if (t + 1 < T_) {
            int wid = bid * (NTHREADS / 32) + (tid >> 5);
            int lane = tid & 31;
            for (int task = wid; task < B_ * NH_; task += nblk * (NTHREADS / 32)) {
                int b = task / NH_, h = task - b * NH_;
                float q[2][2], kk2[2][2], vv[2][2];
                #pragma unroll
                for (int s = 0; s < 2; s++) {
                    int row = (b * 2 + s) * QKVW;
                    #pragma unroll
                    for (int dd = 0; dd < 2; dd++) {
                        int d = lane + dd * 32;
                        int col = h * HD_ + d;
                        float qv = bq[col], kv = bk[col], vvv = bv[col];
                        #pragma unroll
                        for (int kc = 0; kc < SK_QKV; kc++) {
                            const float* p = g_qkvp + (size_t)kc * (128 * QKVW) + row;
                            qv  += p[col];
                            kv  += p[H_ + col];
                            vvv += p[2 * H_ + col];
                        }
                        q[s][dd] = qv; kk2[s][dd] = kv; vv[s][dd] = vvv;
                    }
                }
                float s00 = wsum(q[0][0]*kk2[0][0] + q[0][1]*kk2[0][1]) * 0.125f;
                float s01 = wsum(q[0][0]*kk2[1][0] + q[0][1]*kk2[1][1]) * 0.125f;
                float s10 = wsum(q[1][0]*kk2[0][0] + q[1][1]*kk2[0][1]) * 0.125f;
                float s11 = wsum(q[1][0]*kk2[1][0] + q[1][1]*kk2[1][1]) * 0.125f;
                float m0 = fmaxf(s00, s01), m1 = fmaxf(s10, s11);
                float e00 = expf(s00 - m0), e01 = expf(s01 - m0);
                float e10 = expf(s10 - m1), e11 = expf(s11 - m1);
                float r0 = 1.f / (e00 + e01), r1 = 1.f / (e10 + e11);
                float p00 = e00 * r0, p01 = e01 * r0, p10 = e10 * r1, p11 = e11 * r1;
                #pragma unroll
                for (int dd = 0; dd < 2; dd++) {
                    int d = lane + dd * 32;
                    g_ctx[b * (2*H_) + h * HD_ + d]      = p00 * vv[0][dd] + p01 * vv[1][dd];
                    g_ctx[b * (2*H_) + H_ + h * HD_ + d] = p10 * vv[0][dd] + p11 * vv[1][dd];
                }
            }
        }
        for (int idx = idx0; idx < B_ * H_; idx += stride) {
            int b = idx / H_, j = idx - b * H_;
            float gg[4];
            #pragma unroll
            for (int u = 0; u < 4; u++) {
                int col = b * G4H + u * H_ + j;
                float s = g_base[col];
                #pragma unroll
                for (int kc = 0; kc < SK_G; kc++) s += g_gp[(size_t)kc * (B_ * G4H) + col];
                gg[u] = s;
            }
            float iv = sigm(gg[0]);
            float fv = sigm(gg[1]);
            float gv = tanhf(gg[2]);
            float ov = sigm(gg[3]);
            float c = fv * g_c[idx] + iv * gv;
            float h = ov * tanhf(c);
            g_c[idx] = c;
            g_h[idx] = h;
            out[((size_t)t * B_ + b) * H_ + j] = h;
            if (t == T_ - 1) {
                out[((size_t)T_ * B_ + b) * H_ + j]       = h;   // hT
                out[((size_t)(T_ + 1) * B_ + b) * H_ + j] = c;   // cT
            }
        }
        gsync();

        if (t + 1 < T_) {
            // ---- Z: fuse(t+1), C(64x768), K=1536, splitK 12 -----------------
            for (int task = bid; task < 6 * SK_F; task += nblk) {
                int nt = task / SK_F, kc = task % SK_F;
                int n0 = nt * 128;
                mma_gemm<false>(sAh, sAl, sBh, sBl, nullptr,
                    g_ctx, g_ctx, 2 * H_, 1 << 28,
                    WfuseT_hi + (size_t)n0 * 1536, WfuseT_lo + (size_t)n0 * 1536, 1536,
                    kc * 128, 128, g_fp + (size_t)kc * (B_ * H_) + n0, H_);
            }
            gsync();

            // ---- W: combine fuse + select -> newv(t+1) ----------------------
            for (int idx = idx0; idx < B_ * H_; idx += stride) {
                int b = idx / H_, j = idx - b * H_;
                float e = bfuse[j];
                #pragma unroll
                for (int kc = 0; kc < SK_F; kc++) e += g_fp[(size_t)kc * (B_ * H_) + idx];
                int pt = ping[b * T_ + (t + 1)];
                float right = x[((size_t)(t + 1) * B_ + b) * H_ + j];
                g_newvAll[(size_t)(t + 1) * (B_ * H_) + idx] = (pt > 0) ? e : right;
            }
            gsync();
        }
    }
}

// ------------------------- host launch --------------------------------------
extern "C" void kernel_launch(void* const* d_in, const int* in_sizes, int n_in,
                              void* d_out, int out_size)
{
    (void)in_sizes; (void)n_in; (void)out_size;
    const float* question = (const float*)d_in[0];
    const float* answer   = (const float*)d_in[1];
    const float* x        = (const float*)d_in[2];
    const int*   ping     = (const int*)  d_in[3];
    const float* h0       = (const float*)d_in[4];
    const float* c0       = (const float*)d_in[5];
    const float* Wqh      = (const float*)d_in[6];
    const float* bqh      = (const float*)d_in[7];
    const float* Wah      = (const float*)d_in[8];
    const float* bah      = (const float*)d_in[9];
    const float* Wih      = (const float*)d_in[10];
    const float* bih      = (const float*)d_in[11];
    const float* Whh      = (const float*)d_in[12];
    const float* bhh      = (const float*)d_in[13];
    const float* Wq       = (const float*)d_in[14];
    const float* bq       = (const float*)d_in[15];
    const float* Wk       = (const float*)d_in[16];
    const float* bk       = (const float*)d_in[17];
    const float* Wv       = (const float*)d_in[18];
    const float* bv       = (const float*)d_in[19];
    const float* Wfuse    = (const float*)d_in[20];
    const float* bfuse    = (const float*)d_in[21];

    int dev = 0;
    cudaGetDevice(&dev);
    int nsm = 148;
    cudaDeviceGetAttribute(&nsm, cudaDevAttrMultiProcessorCount, dev);

    prep_kernel<<<nsm * 8, 256>>>(Wqh, Wah, Wih, Whh, Wq, Wk, Wv, Wfuse);

    sqac_kernel<<<nsm * 2, NTHREADS>>>(question, answer, x, ping, h0, c0,
                                       bqh, bah, bih, bhh,
                                       bq, bk, bv, bfuse,
                                       (float*)d_out);
}

// round 6
// speedup vs baseline: 1.9953x; 1.1770x over previous
#include <cuda_runtime.h>
#include <cuda_bf16.h>
#include <math.h>
#include <stdint.h>

#define T_  256
#define B_  64
#define H_  768
#define NH_ 12
#define HD_ 64
#define G4H 3072
#define QKVW 2304
#define NTHREADS 256
#define SK_G 6
#define SK_Q 4
#define SK_F 12

// fragment-array strides (uint2 units) per task
#define TSK_G (16*16*64)
#define TSK_Q (12*8*64)
#define TSK_F (8*8*64)
// smem byte offsets
#define SOFF_WQ 131072
#define SOFF_WF 180224
#define SOFF_A  212992
#define SOFF_RP 229376
#define SMEM_TOTAL 230400

__device__ __align__(256) float g_newvAll[T_*B_*H_];
__device__ __align__(256) float g_qkvp[SK_Q*2*B_*QKVW];
__device__ __align__(256) float g_ctx[B_*2*H_];
__device__ __align__(256) float g_fp[SK_F*B_*H_];
__device__ __align__(256) float g_gp[SK_G*B_*G4H];
__device__ __align__(256) float g_base[B_*G4H];
__device__ __align__(256) float g_h[B_*H_];
__device__ __align__(256) float g_c[B_*H_];
__device__ unsigned g_cnt = 0;
__device__ unsigned g_gen = 0;

__device__ __align__(256) uint2 WbaseF[144*TSK_G];
__device__ __align__(256) uint2 WgF[144*TSK_G];
__device__ __align__(256) uint2 WqF[144*TSK_Q];
__device__ __align__(256) uint2 WfF[144*TSK_F];

__device__ __forceinline__ void gsync() {
    __syncthreads();
    if (threadIdx.x == 0) {
        __threadfence();
        unsigned g = *(volatile unsigned*)&g_gen;
        unsigned a = atomicAdd(&g_cnt, 1u);
        if (a == gridDim.x - 1u) {
            *(volatile unsigned*)&g_cnt = 0u;
            __threadfence();
            *(volatile unsigned*)&g_gen = g + 1u;
        } else {
            while (*(volatile unsigned*)&g_gen == g) { }
        }
        __threadfence();
    }
    __syncthreads();
}
__device__ __forceinline__ float wsum(float v) {
    #pragma unroll
    for (int o = 16; o > 0; o >>= 1) v += __shfl_xor_sync(0xffffffffu, v, o);
    return v;
}
__device__ __forceinline__ float sigm(float v) { return 1.f / (1.f + expf(-v)); }
__device__ __forceinline__ uint32_t pkhi(float a, float b) {
    __nv_bfloat162 t = __floats2bfloat162_rn(a, b);
    return *(uint32_t*)&t;
}
__device__ __forceinline__ uint32_t pklo(float a, float b) {
    float ra = a - __bfloat162float(__float2bfloat16(a));
    float rb = b - __bfloat162float(__float2bfloat16(b));
    return pkhi(ra, rb);
}
__device__ __forceinline__ void split2(float2 v, uint32_t& h, uint32_t& l) {
    h = pkhi(v.x, v.y);
    l = pklo(v.x, v.y);
}
__device__ __forceinline__ void mma16816(float* c, const uint32_t* a, const uint32_t* b) {
    asm volatile(
        "mma.sync.aligned.m16n8k16.row.col.f32.bf16.bf16.f32 "
        "{%0,%1,%2,%3}, {%4,%5,%6,%7}, {%8,%9}, {%0,%1,%2,%3};"
        : "+f"(c[0]), "+f"(c[1]), "+f"(c[2]), "+f"(c[3])
        : "r"(a[0]), "r"(a[1]), "r"(a[2]), "r"(a[3]), "r"(b[0]), "r"(b[1]));
}

// stage one A fragment (hi at slot+lane, lo at slot+32+lane)
__device__ __forceinline__ void stA_slot(uint4* sA, int slotBase, int lane,
                                         const float* p1, const float* p2, int c1) {
    float2 v00 = *(const float2*)(p1 + c1);
    float2 v01 = *(const float2*)(p1 + c1 + 8);
    float2 v10 = *(const float2*)(p2 + c1);
    float2 v11 = *(const float2*)(p2 + c1 + 8);
    uint4 Hv, Lv;
    split2(v00, Hv.x, Lv.x);
    split2(v10, Hv.y, Lv.y);
    split2(v01, Hv.z, Lv.z);
    split2(v11, Hv.w, Lv.w);
    sA[slotBase + lane]      = Hv;
    sA[slotBase + 32 + lane] = Lv;
}
// 64-row A, 32-k stage
__device__ __forceinline__ void stageA_g(uint4* sA, int buf, const float* Ab, int lda, int c0) {
    const int tid = threadIdx.x;
    const int kt = tid >> 7, mt = (tid >> 5) & 3, lane = tid & 31;
    const int rr = lane >> 2, kp = lane & 3;
    const float* p1 = Ab + (size_t)(mt * 16 + rr) * lda;
    stA_slot(sA, ((buf * 2 + kt) * 4 + mt) * 64, lane, p1, p1 + 8 * lda, c0 + kt * 16 + kp * 2);
}
// 128-row A via row pointers, 16-k stage
__device__ __forceinline__ void stageA_q(uint4* sA, int buf, const float* const* rowp, int c0) {
    const int tid = threadIdx.x;
    const int mt = tid >> 5, lane = tid & 31;
    const int rr = lane >> 2, kp = lane & 3;
    stA_slot(sA, (buf * 8 + mt) * 64, lane, rowp[mt * 16 + rr], rowp[mt * 16 + rr + 8],
             c0 + kp * 2);
}

template<int KTPS, int MTOT, int NWARP, int NJ, int NGTOT>
__device__ __forceinline__ void comp_stage(const uint4* sA, const uint2* sW,
                                           int buf, int s, float acc[2][NJ][4]) {
    const int w = threadIdx.x >> 5, lane = threadIdx.x & 31;
    const int mw = w / NWARP, nw = w % NWARP;
    #pragma unroll
    for (int kt = 0; kt < KTPS; kt++) {
        const int ktg = s * KTPS + kt;
        uint4 ah[2], al[2];
        #pragma unroll
        for (int i = 0; i < 2; i++) {
            int sl = ((buf * KTPS + kt) * MTOT + mw * 2 + i) * 64;
            ah[i] = sA[sl + lane];
            al[i] = sA[sl + 32 + lane];
        }
        #pragma unroll
        for (int j = 0; j < NJ; j++) {
            const uint2* wb = sW + (size_t)(ktg * NGTOT + nw * NJ + j) * 64;
            uint2 bh = wb[lane];
            uint2 bl = wb[32 + lane];
            #pragma unroll
            for (int i = 0; i < 2; i++) {
                mma16816(acc[i][j], (const uint32_t*)&ah[i], (const uint32_t*)&bh);
                mma16816(acc[i][j], (const uint32_t*)&ah[i], (const uint32_t*)&bl);
                mma16816(acc[i][j], (const uint32_t*)&al[i], (const uint32_t*)&bh);
            }
        }
    }
}
template<int NWARP, int NJ>
__device__ __forceinline__ void epi(const float acc[2][NJ][4], float* C, int ldc) {
    const int w = threadIdx.x >> 5, lane = threadIdx.x & 31;
    const int mw = w / NWARP, nw = w % NWARP;
    const int g = lane >> 2, tg = lane & 3;
    #pragma unroll
    for (int i = 0; i < 2; i++)
        #pragma unroll
        for (int j = 0; j < NJ; j++) {
            float* d0 = C + (size_t)((mw * 2 + i) * 16 + g) * ldc + (nw * NJ + j) * 8 + 2 * tg;
            *(float2*)d0             = make_float2(acc[i][j][0], acc[i][j][1]);
            *(float2*)(d0 + 8 * ldc) = make_float2(acc[i][j][2], acc[i][j][3]);
        }
}

__global__ void prep_kernel(const float* __restrict__ Wqh, const float* __restrict__ Wah,
                            const float* __restrict__ Wih, const float* __restrict__ Whh,
                            const float* __restrict__ Wq,  const float* __restrict__ Wk,
                            const float* __restrict__ Wv,  const float* __restrict__ Wfuse)
{
    const int idx0 = blockIdx.x * blockDim.x + threadIdx.x;
    const int stride = gridDim.x * blockDim.x;
    const int EG = 144 * 16 * 16 * 32;
    for (int e = idx0; e < EG; e += stride) {
        int lane = e & 31; int r = e >> 5;
        int ng = r & 15; r >>= 4;
        int kt = r & 15; r >>= 4;
        int task = r;
        int nt = task / 6, kc = task % 6;
        int n = nt * 128 + ng * 8 + (lane >> 2);
        int k = kc * 256 + kt * 16 + ((lane & 3) << 1);
        size_t o = (size_t)task * TSK_G + (kt * 16 + ng) * 64 + lane;
        {
            float v0, v1, v2, v3;
            if (k < H_) { v0 = Wqh[(size_t)k*G4H+n]; v1 = Wqh[(size_t)(k+1)*G4H+n];
                          v2 = Wqh[(size_t)(k+8)*G4H+n]; v3 = Wqh[(size_t)(k+9)*G4H+n]; }
            else { int kk = k - H_; v0 = Wah[(size_t)kk*G4H+n]; v1 = Wah[(size_t)(kk+1)*G4H+n];
                   v2 = Wah[(size_t)(kk+8)*G4H+n]; v3 = Wah[(size_t)(kk+9)*G4H+n]; }
            WbaseF[o]      = make_uint2(pkhi(v0, v1), pkhi(v2, v3));
            WbaseF[o + 32] = make_uint2(pklo(v0, v1), pklo(v2, v3));
        }
        {
            float v0, v1, v2, v3;
            if (k < H_) { v0 = Wih[(size_t)k*G4H+n]; v1 = Wih[(size_t)(k+1)*G4H+n];
                          v2 = Wih[(size_t)(k+8)*G4H+n]; v3 = Wih[(size_t)(k+9)*G4H+n]; }
            else { int kk = k - H_; v0 = Whh[(size_t)kk*G4H+n]; v1 = Whh[(size_t)(kk+1)*G4H+n];
                   v2 = Whh[(size_t)(kk+8)*G4H+n]; v3 = Whh[(size_t)(kk+9)*G4H+n]; }
            WgF[o]      = make_uint2(pkhi(v0, v1), pkhi(v2, v3));
            WgF[o + 32] = make_uint2(pklo(v0, v1), pklo(v2, v3));
        }
    }
    const int EQ = 144 * 12 * 8 * 32;
    for (int e = idx0; e < EQ; e += stride) {
        int lane = e & 31; int r = e >> 5;
        int ng = r & 7; r >>= 3;
        int kt = r % 12; int task = r / 12;
        int nt = task / 4, kc = task % 4;
        int n = nt * 64 + ng * 8 + (lane >> 2);
        int k = kc * 192 + kt * 16 + ((lane & 3) << 1);
        int ws = n / H_, nc = n - ws * H_;
        const float* W = (ws == 0) ? Wq : ((ws == 1) ? Wk : Wv);
        float v0 = W[(size_t)k*H_+nc],     v1 = W[(size_t)(k+1)*H_+nc];
        float v2 = W[(size_t)(k+8)*H_+nc], v3 = W[(size_t)(k+9)*H_+nc];
        size_t o = (size_t)task * TSK_Q + (kt * 8 + ng) * 64 + lane;
        WqF[o]      = make_uint2(pkhi(v0, v1), pkhi(v2, v3));
        WqF[o + 32] = make_uint2(pklo(v0, v1), pklo(v2, v3));
    }
    const int EF = 144 * 8 * 8 * 32;
    for (int e = idx0; e < EF; e += stride) {
        int lane = e & 31; int r = e >> 5;
        int ng = r & 7; r >>= 3;
        int kt = r & 7; r >>= 3;
        int task = r;
        int nt = task / 12, kc = task % 12;
        int n = nt * 64 + ng * 8 + (lane >> 2);
        int k = kc * 128 + kt * 16 + ((lane & 3) << 1);
        float v0 = Wfuse[(size_t)k*H_+n],     v1 = Wfuse[(size_t)(k+1)*H_+n];
        float v2 = Wfuse[(size_t)(k+8)*H_+n], v3 = Wfuse[(size_t)(k+9)*H_+n];
        size_t o = (size_t)task * TSK_F + (kt * 8 + ng) * 64 + lane;
        WfF[o]      = make_uint2(pkhi(v0, v1), pkhi(v2, v3));
        WfF[o + 32] = make_uint2(pklo(v0, v1), pklo(v2, v3));
    }
}

__global__ void __launch_bounds__(NTHREADS, 1)
sqac_kernel(const float* __restrict__ question, const float* __restrict__ answer,
            const float* __restrict__ x, const int* __restrict__ ping,
            const float* __restrict__ h0, const float* __restrict__ c0,
            const float* __restrict__ bqh, const float* __restrict__ bah,
            const float* __restrict__ bih, const float* __restrict__ bhh,
            const float* __restrict__ bq,  const float* __restrict__ bk,
            const float* __restrict__ bv,  const float* __restrict__ bfuse,
            float* __restrict__ out)
{
    extern __shared__ __align__(16) char smem[];
    uint2* sWg = (uint2*)smem;
    uint2* sWq = (uint2*)(smem + SOFF_WQ);
    uint2* sWf = (uint2*)(smem + SOFF_WF);
    uint4* sA  = (uint4*)(smem + SOFF_A);
    const float** rowp = (const float**)(smem + SOFF_RP);

    const int idx0   = blockIdx.x * blockDim.x + threadIdx.x;
    const int stride = gridDim.x * blockDim.x;
    const int bid    = blockIdx.x;
    const int nblk   = gridDim.x;
    const int tid    = threadIdx.x;

    // ---- prologue: pin weights, init state, base GEMM --------------------
    if (bid < 144) {
        const uint4* s1 = (const uint4*)(WbaseF + (size_t)bid * TSK_G);
        for (int i = tid; i < TSK_G / 2; i += NTHREADS) ((uint4*)sWg)[i] = s1[i];
        const uint4* s2 = (const uint4*)(WqF + (size_t)bid * TSK_Q);
        for (int i = tid; i < TSK_Q / 2; i += NTHREADS) ((uint4*)sWq)[i] = s2[i];
        const uint4* s3 = (const uint4*)(WfF + (size_t)bid * TSK_F);
        for (int i = tid; i < TSK_F / 2; i += NTHREADS) ((uint4*)sWf)[i] = s3[i];
    }
    for (int idx = idx0; idx < B_ * H_; idx += stride) {
        g_h[idx] = h0[idx];
        g_c[idx] = c0[idx];
        g_newvAll[idx] = x[idx];
    }
    __syncthreads();

    if (bid < 144) {
        const int nt = bid / 6, kc = bid % 6;
        const float* Ab = (kc < 3) ? (question + kc * 256) : (answer + (kc - 3) * 256);
        float acc[2][4][4] = {};
        stageA_g(sA, 0, Ab, H_, 0);
        __syncthreads();
        for (int s = 0; s < 8; s++) {
            if (s < 7) stageA_g(sA, (s + 1) & 1, Ab, H_, (s + 1) * 32);
            comp_stage<2, 4, 4, 4, 16>(sA, sWg, s & 1, s, acc);
            __syncthreads();
        }
        epi<4, 4>(acc, g_gp + (size_t)kc * (B_ * G4H) + nt * 128, G4H);
        __syncthreads();
        const uint4* s1 = (const uint4*)(WgF + (size_t)bid * TSK_G);
        for (int i = tid; i < TSK_G / 2; i += NTHREADS) ((uint4*)sWg)[i] = s1[i];
    }
    gsync();

    for (int idx = idx0; idx < B_ * G4H; idx += stride) {
        int n = idx % G4H;
        float s = bqh[n] + bah[n] + bih[n] + bhh[n];
        #pragma unroll
        for (int kc = 0; kc < SK_G; kc++) s += g_gp[(size_t)kc * (B_ * G4H) + idx];
        g_base[idx] = s;
    }
    gsync();

    // =======================================================================
    for (int t = 0; t < T_; t++) {
        // ---- X: gates(t) + QKV(t+1) on pinned weights ---------------------
        if (bid < 144) {
            {
                const int nt = bid / 6, kc = bid % 6;
                const float* Ab = (kc < 3) ? (g_newvAll + (size_t)t * (B_ * H_) + kc * 256)
                                           : (g_h + (kc - 3) * 256);
                float acc[2][4][4] = {};
                stageA_g(sA, 0, Ab, H_, 0);
                __syncthreads();
                for (int s = 0; s < 8; s++) {
                    if (s < 7) stageA_g(sA, (s + 1) & 1, Ab, H_, (s + 1) * 32);
                    comp_stage<2, 4, 4, 4, 16>(sA, sWg, s & 1, s, acc);
                    __syncthreads();
                }
                epi<4, 4>(acc, g_gp + (size_t)kc * (B_ * G4H) + nt * 128, G4H);
                __syncthreads();
            }
            if (t + 1 < T_) {
                if (tid < 128) {
                    int m = tid, b = m >> 1, s2 = m & 1;
                    const float* p;
                    if (s2) {
                        p = x + ((size_t)(t + 1) * B_ + b) * H_;
                    } else {
                        int pt = ping[b * T_ + (t + 1)];
                        int i2 = pt - 1;
                        i2 = i2 < 0 ? 0 : (i2 > T_ - 1 ? T_ - 1 : i2);
                        p = ((i2 <= t) ? g_newvAll : x) + ((size_t)i2 * B_ + b) * H_;
                    }
                    rowp[m] = p;
                }
                __syncthreads();
                const int nt = bid / 4, kc = bid % 4;
                const int c0 = kc * 192;
                float acc[2][4][4] = {};
                stageA_q(sA, 0, rowp, c0);
                __syncthreads();
                for (int s = 0; s < 12; s++) {
                    if (s < 11) stageA_q(sA, (s + 1) & 1, rowp, c0 + (s + 1) * 16);
                    comp_stage<1, 8, 2, 4, 8>(sA, sWq, s & 1, s, acc);
                    __syncthreads();
                }
                epi<2, 4>(acc, g_qkvp + (size_t)kc * (2 * B_ * QKVW) + nt * 64, QKVW);
            }
        }
        gsync();

        // ---- Y: attention(t+1) + LSTM pointwise(t) -------------------------
        if (t + 1 < T_) {
            int wid = bid * (NTHREADS / 32) + (tid >> 5);
            int lane = tid & 31;
            for (int task = wid; task < B_ * NH_; task += nblk * (NTHREADS / 32)) {
                int b = task / NH_, h = task - b * NH_;
                float q[2][2], kk2[2][2], vv[2][2];
                #pragma unroll
                for (int s = 0; s < 2; s++) {
                    int row = (b * 2 + s) * QKVW;
                    #pragma unroll
                    for (int dd = 0; dd < 2; dd++) {
                        int col = h * HD_ + lane + dd * 32;
                        float qv = bq[col], kv = bk[col], vvv = bv[col];
                        #pragma unroll
                        for (int kc = 0; kc < SK_Q; kc++) {
                            const float* p = g_qkvp + (size_t)kc * (2 * B_ * QKVW) + row;
                            qv  += p[col];
                            kv  += p[H_ + col];
                            vvv += p[2 * H_ + col];
                        }
                        q[s][dd] = qv; kk2[s][dd] = kv; vv[s][dd] = vvv;
                    }
                }
                float s00 = wsum(q[0][0]*kk2[0][0] + q[0][1]*kk2[0][1]) * 0.125f;
                float s01 = wsum(q[0][0]*kk2[1][0] + q[0][1]*kk2[1][1]) * 0.125f;
                float s10 = wsum(q[1][0]*kk2[0][0] + q[1][1]*kk2[0][1]) * 0.125f;
                float s11 = wsum(q[1][0]*kk2[1][0] + q[1][1]*kk2[1][1]) * 0.125f;
                float m0 = fmaxf(s00, s01), m1 = fmaxf(s10, s11);
                float e00 = expf(s00 - m0), e01 = expf(s01 - m0);
                float e10 = expf(s10 - m1), e11 = expf(s11 - m1);
                float r0 = 1.f / (e00 + e01), r1 = 1.f / (e10 + e11);
                float p00 = e00 * r0, p01 = e01 * r0, p10 = e10 * r1, p11 = e11 * r1;
                #pragma unroll
                for (int dd = 0; dd < 2; dd++) {
                    int d = lane + dd * 32;
                    g_ctx[b * (2*H_) + h * HD_ + d]      = p00 * vv[0][dd] + p01 * vv[1][dd];
                    g_ctx[b * (2*H_) + H_ + h * HD_ + d] = p10 * vv[0][dd] + p11 * vv[1][dd];
                }
            }
        }
        for (int idx = idx0; idx < B_ * H_; idx += stride) {
            int b = idx / H_, j = idx - b * H_;
            float gg[4];
            #pragma unroll
            for (int u = 0; u < 4; u++) {
                int col = b * G4H + u * H_ + j;
                float s = g_base[col];
                #pragma unroll
                for (int kc = 0; kc < SK_G; kc++) s += g_gp[(size_t)kc * (B_ * G4H) + col];
                gg[u] = s;
            }
            float iv = sigm(gg[0]);
            float fv = sigm(gg[1]);
            float gv = tanhf(gg[2]);
            float ov = sigm(gg[3]);
            float c = fv * g_c[idx] + iv * gv;
            float h = ov * tanhf(c);
            g_c[idx] = c;
            g_h[idx] = h;
            out[((size_t)t * B_ + b) * H_ + j] = h;
            if (t == T_ - 1) {
                out[((size_t)T_ * B_ + b) * H_ + j]       = h;
                out[((size_t)(T_ + 1) * B_ + b) * H_ + j] = c;
            }
        }
        gsync();

        if (t + 1 < T_) {
            // ---- Z: fuse(t+1) on pinned weights ------------------------------
            if (bid < 144) {
                const int nt = bid / 12, kc = bid % 12;
                const float* Ab = g_ctx + kc * 128;
                float acc[2][2][4] = {};
                stageA_g(sA, 0, Ab, 2 * H_, 0);
                __syncthreads();
                for (int s = 0; s < 4; s++) {
                    if (s < 3) stageA_g(sA, (s + 1) & 1, Ab, 2 * H_, (s + 1) * 32);
                    comp_stage<2, 4, 4, 2, 8>(sA, sWf, s & 1, s, acc);
                    __syncthreads();
                }
                epi<4, 2>(acc, g_fp + (size_t)kc * (B_ * H_) + nt * 64, H_);
            }
            gsync();

            // ---- W: combine fuse + select -> newv(t+1) ------------------------
            for (int idx = idx0; idx < B_ * H_; idx += stride) {
                int b = idx / H_, j = idx - b * H_;
                float e = bfuse[j];
                #pragma unroll
                for (int kc = 0; kc < SK_F; kc++) e += g_fp[(size_t)kc * (B_ * H_) + idx];
                int pt = ping[b * T_ + (t + 1)];
                float right = x[((size_t)(t + 1) * B_ + b) * H_ + j];
                g_newvAll[(size_t)(t + 1) * (B_ * H_) + idx] = (pt > 0) ? e : right;
            }
            gsync();
        }
    }
}

extern "C" void kernel_launch(void* const* d_in, const int* in_sizes, int n_in,
                              void* d_out, int out_size)
{
    (void)in_sizes; (void)n_in; (void)out_size;
    const float* question = (const float*)d_in[0];
    const float* answer   = (const float*)d_in[1];
    const float* x        = (const float*)d_in[2];
    const int*   ping     = (const int*)  d_in[3];
    const float* h0       = (const float*)d_in[4];
    const float* c0       = (const float*)d_in[5];
    const float* Wqh      = (const float*)d_in[6];
    const float* bqh      = (const float*)d_in[7];
    const float* Wah      = (const float*)d_in[8];
    const float* bah      = (const float*)d_in[9];
    const float* Wih      = (const float*)d_in[10];
    const float* bih      = (const float*)d_in[11];
    const float* Whh      = (const float*)d_in[12];
    const float* bhh      = (const float*)d_in[13];
    const float* Wq       = (const float*)d_in[14];
    const float* bq       = (const float*)d_in[15];
    const float* Wk       = (const float*)d_in[16];
    const float* bk       = (const float*)d_in[17];
    const float* Wv       = (const float*)d_in[18];
    const float* bv       = (const float*)d_in[19];
    const float* Wfuse    = (const float*)d_in[20];
    const float* bfuse    = (const float*)d_in[21];

    int dev = 0;
    cudaGetDevice(&dev);
    int nsm = 148;
    cudaDeviceGetAttribute(&nsm, cudaDevAttrMultiProcessorCount, dev);

    cudaFuncSetAttribute(sqac_kernel, cudaFuncAttributeMaxDynamicSharedMemorySize, SMEM_TOTAL);

    prep_kernel<<<nsm * 8, 256>>>(Wqh, Wah, Wih, Whh, Wq, Wk, Wv, Wfuse);
    sqac_kernel<<<nsm, NTHREADS, SMEM_TOTAL>>>(question, answer, x, ping, h0, c0,
                                               bqh, bah, bih, bhh, bq, bk, bv, bfuse,
                                               (float*)d_out);
}

// round 7
// speedup vs baseline: 2.1489x; 1.0770x over previous
#include <cuda_runtime.h>
#include <cuda_bf16.h>
#include <math.h>
#include <stdint.h>

#define T_  256
#define B_  64
#define H_  768
#define NH_ 12
#define HD_ 64
#define G4H 3072
#define QKVW 2304
#define NTHREADS 512
#define SK_G 6
#define SK_Q 4
#define SK_F 12

#define TSK_G (16*16*64)
#define TSK_Q (12*8*64)
#define TSK_F (8*8*64)
#define SOFF_WQ 131072
#define SOFF_WF 180224
#define SOFF_A  212992
#define SOFF_RP 229376
#define SMEM_TOTAL 230400

__device__ __align__(256) float g_newvAll[T_*B_*H_];
__device__ __align__(256) float g_qkvp[SK_Q*2*B_*QKVW];
__device__ __align__(256) float g_ctx[B_*2*H_];
__device__ __align__(256) float g_fp[SK_F*B_*H_];
__device__ __align__(256) float g_gp[SK_G*B_*G4H];
__device__ __align__(256) float g_base[B_*G4H];
__device__ __align__(256) float g_h[B_*H_];
__device__ __align__(256) float g_c[B_*H_];
__device__ unsigned g_cnt = 0;
__device__ unsigned g_gen = 0;

__device__ __align__(256) uint2 WbaseF[144*TSK_G];
__device__ __align__(256) uint2 WgF[144*TSK_G];
__device__ __align__(256) uint2 WqF[144*TSK_Q];
__device__ __align__(256) uint2 WfF[144*TSK_F];

__device__ __forceinline__ void gsync() {
    __syncthreads();
    if (threadIdx.x == 0) {
        __threadfence();
        unsigned g = *(volatile unsigned*)&g_gen;
        unsigned a = atomicAdd(&g_cnt, 1u);
        if (a == gridDim.x - 1u) {
            *(volatile unsigned*)&g_cnt = 0u;
            __threadfence();
            *(volatile unsigned*)&g_gen = g + 1u;
        } else {
            while (*(volatile unsigned*)&g_gen == g) { }
        }
        __threadfence();
    }
    __syncthreads();
}
__device__ __forceinline__ float wsum(float v) {
    #pragma unroll
    for (int o = 16; o > 0; o >>= 1) v += __shfl_xor_sync(0xffffffffu, v, o);
    return v;
}
__device__ __forceinline__ float sigm(float v) { return 1.f / (1.f + expf(-v)); }
__device__ __forceinline__ uint32_t pkhi(float a, float b) {
    __nv_bfloat162 t = __floats2bfloat162_rn(a, b);
    return *(uint32_t*)&t;
}
__device__ __forceinline__ uint32_t pklo(float a, float b) {
    float ra = a - __bfloat162float(__float2bfloat16(a));
    float rb = b - __bfloat162float(__float2bfloat16(b));
    return pkhi(ra, rb);
}
__device__ __forceinline__ void split2(float2 v, uint32_t& h, uint32_t& l) {
    h = pkhi(v.x, v.y);
    l = pklo(v.x, v.y);
}
__device__ __forceinline__ void mma16816(float* c, const uint32_t* a, const uint32_t* b) {
    asm volatile(
        "mma.sync.aligned.m16n8k16.row.col.f32.bf16.bf16.f32 "
        "{%0,%1,%2,%3}, {%4,%5,%6,%7}, {%8,%9}, {%0,%1,%2,%3};"
        : "+f"(c[0]), "+f"(c[1]), "+f"(c[2]), "+f"(c[3])
        : "r"(a[0]), "r"(a[1]), "r"(a[2]), "r"(a[3]), "r"(b[0]), "r"(b[1]));
}

__device__ __forceinline__ void stA_slot(uint4* sA, int slotBase, int lane,
                                         const float* p1, const float* p2, int c1) {
    float2 v00 = *(const float2*)(p1 + c1);
    float2 v01 = *(const float2*)(p1 + c1 + 8);
    float2 v10 = *(const float2*)(p2 + c1);
    float2 v11 = *(const float2*)(p2 + c1 + 8);
    uint4 Hv, Lv;
    split2(v00, Hv.x, Lv.x);
    split2(v10, Hv.y, Lv.y);
    split2(v01, Hv.z, Lv.z);
    split2(v11, Hv.w, Lv.w);
    sA[slotBase + lane]      = Hv;
    sA[slotBase + 32 + lane] = Lv;
}
// 64-row A, 32-k stage (first 256 threads)
__device__ __forceinline__ void stageA_g(uint4* sA, int buf, const float* Ab, int lda, int c0) {
    const int tid = threadIdx.x;
    if (tid >= 256) return;
    const int kt = tid >> 7, mt = (tid >> 5) & 3, lane = tid & 31;
    const int rr = lane >> 2, kp = lane & 3;
    const float* p1 = Ab + (size_t)(mt * 16 + rr) * lda;
    stA_slot(sA, ((buf * 2 + kt) * 4 + mt) * 64, lane, p1, p1 + 8 * lda, c0 + kt * 16 + kp * 2);
}
// 128-row A via row pointers, 16-k stage (first 256 threads)
__device__ __forceinline__ void stageA_q(uint4* sA, int buf, const float* const* rowp, int c0) {
    const int tid = threadIdx.x;
    if (tid >= 256) return;
    const int mt = tid >> 5, lane = tid & 31;
    const int rr = lane >> 2, kp = lane & 3;
    stA_slot(sA, (buf * 8 + mt) * 64, lane, rowp[mt * 16 + rr], rowp[mt * 16 + rr + 8],
             c0 + kp * 2);
}

// 16 warps: MI=1 (one m16 tile per warp). warp grid: (16/NWARP) m x NWARP n
template<int KTPS, int MTOT, int NWARP, int NJ, int NGTOT>
__device__ __forceinline__ void comp_stage(const uint4* sA, const uint2* sW,
                                           int buf, int s, float acc[NJ][4]) {
    const int w = threadIdx.x >> 5, lane = threadIdx.x & 31;
    const int mw = w / NWARP, nw = w % NWARP;
    #pragma unroll
    for (int kt = 0; kt < KTPS; kt++) {
        const int ktg = s * KTPS + kt;
        const int sl = ((buf * KTPS + kt) * MTOT + mw) * 64;
        uint4 ah = sA[sl + lane];
        uint4 al = sA[sl + 32 + lane];
        #pragma unroll
        for (int j = 0; j < NJ; j++) {
            const uint2* wb = sW + (size_t)(ktg * NGTOT + nw * NJ + j) * 64;
            uint2 bh = wb[lane];
            uint2 bl = wb[32 + lane];
            mma16816(acc[j], (const uint32_t*)&ah, (const uint32_t*)&bh);
            mma16816(acc[j], (const uint32_t*)&ah, (const uint32_t*)&bl);
            mma16816(acc[j], (const uint32_t*)&al, (const uint32_t*)&bh);
        }
    }
}
template<int NWARP, int NJ>
__device__ __forceinline__ void epi(const float acc[NJ][4], float* C, int ldc) {
    const int w = threadIdx.x >> 5, lane = threadIdx.x & 31;
    const int mw = w / NWARP, nw = w % NWARP;
    const int g = lane >> 2, tg = lane & 3;
    #pragma unroll
    for (int j = 0; j < NJ; j++) {
        float* d0 = C + (size_t)(mw * 16 + g) * ldc + (nw * NJ + j) * 8 + 2 * tg;
        *(float2*)d0             = make_float2(acc[j][0], acc[j][1]);
        *(float2*)(d0 + 8 * ldc) = make_float2(acc[j][2], acc[j][3]);
    }
}

__global__ void prep_kernel(const float* __restrict__ Wqh, const float* __restrict__ Wah,
                            const float* __restrict__ Wih, const float* __restrict__ Whh,
                            const float* __restrict__ Wq,  const float* __restrict__ Wk,
                            const float* __restrict__ Wv,  const float* __restrict__ Wfuse)
{
    const int idx0 = blockIdx.x * blockDim.x + threadIdx.x;
    const int stride = gridDim.x * blockDim.x;
    const int EG = 144 * 16 * 16 * 32;
    for (int e = idx0; e < EG; e += stride) {
        int lane = e & 31; int r = e >> 5;
        int ng = r & 15; r >>= 4;
        int kt = r & 15; r >>= 4;
        int task = r;
        int nt = task / 6, kc = task % 6;
        int n = nt * 128 + ng * 8 + (lane >> 2);
        int k = kc * 256 + kt * 16 + ((lane & 3) << 1);
        size_t o = (size_t)task * TSK_G + (kt * 16 + ng) * 64 + lane;
        {
            float v0, v1, v2, v3;
            if (k < H_) { v0 = Wqh[(size_t)k*G4H+n]; v1 = Wqh[(size_t)(k+1)*G4H+n];
                          v2 = Wqh[(size_t)(k+8)*G4H+n]; v3 = Wqh[(size_t)(k+9)*G4H+n]; }
            else { int kk = k - H_; v0 = Wah[(size_t)kk*G4H+n]; v1 = Wah[(size_t)(kk+1)*G4H+n];
                   v2 = Wah[(size_t)(kk+8)*G4H+n]; v3 = Wah[(size_t)(kk+9)*G4H+n]; }
            WbaseF[o]      = make_uint2(pkhi(v0, v1), pkhi(v2, v3));
            WbaseF[o + 32] = make_uint2(pklo(v0, v1), pklo(v2, v3));
        }
        {
            float v0, v1, v2, v3;
            if (k < H_) { v0 = Wih[(size_t)k*G4H+n]; v1 = Wih[(size_t)(k+1)*G4H+n];
                          v2 = Wih[(size_t)(k+8)*G4H+n]; v3 = Wih[(size_t)(k+9)*G4H+n]; }
            else { int kk = k - H_; v0 = Whh[(size_t)kk*G4H+n]; v1 = Whh[(size_t)(kk+1)*G4H+n];
                   v2 = Whh[(size_t)(kk+8)*G4H+n]; v3 = Whh[(size_t)(kk+9)*G4H+n]; }
            WgF[o]      = make_uint2(pkhi(v0, v1), pkhi(v2, v3));
            WgF[o + 32] = make_uint2(pklo(v0, v1), pklo(v2, v3));
        }
    }
    const int EQ = 144 * 12 * 8 * 32;
    for (int e = idx0; e < EQ; e += stride) {
        int lane = e & 31; int r = e >> 5;
        int ng = r & 7; r >>= 3;
        int kt = r % 12; int task = r / 12;
        int nt = task / 4, kc = task % 4;
        int n = nt * 64 + ng * 8 + (lane >> 2);
        int k = kc * 192 + kt * 16 + ((lane & 3) << 1);
        int ws = n / H_, nc = n - ws * H_;
        const float* W = (ws == 0) ? Wq : ((ws == 1) ? Wk : Wv);
        float v0 = W[(size_t)k*H_+nc],     v1 = W[(size_t)(k+1)*H_+nc];
        float v2 = W[(size_t)(k+8)*H_+nc], v3 = W[(size_t)(k+9)*H_+nc];
        size_t o = (size_t)task * TSK_Q + (kt * 8 + ng) * 64 + lane;
        WqF[o]      = make_uint2(pkhi(v0, v1), pkhi(v2, v3));
        WqF[o + 32] = make_uint2(pklo(v0, v1), pklo(v2, v3));
    }
    const int EF = 144 * 8 * 8 * 32;
    for (int e = idx0; e < EF; e += stride) {
        int lane = e & 31; int r = e >> 5;
        int ng = r & 7; r >>= 3;
        int kt = r & 7; r >>= 3;
        int task = r;
        int nt = task / 12, kc = task % 12;
        int n = nt * 64 + ng * 8 + (lane >> 2);
        int k = kc * 128 + kt * 16 + ((lane & 3) << 1);
        float v0 = Wfuse[(size_t)k*H_+n],     v1 = Wfuse[(size_t)(k+1)*H_+n];
        float v2 = Wfuse[(size_t)(k+8)*H_+n], v3 = Wfuse[(size_t)(k+9)*H_+n];
        size_t o = (size_t)task * TSK_F + (kt * 8 + ng) * 64 + lane;
        WfF[o]      = make_uint2(pkhi(v0, v1), pkhi(v2, v3));
        WfF[o + 32] = make_uint2(pklo(v0, v1), pklo(v2, v3));
    }
}

__global__ void __launch_bounds__(NTHREADS, 1)
sqac_kernel(const float* __restrict__ question, const float* __restrict__ answer,
            const float* __restrict__ x, const int* __restrict__ ping,
            const float* __restrict__ h0, const float* __restrict__ c0,
            const float* __restrict__ bqh, const float* __restrict__ bah,
            const float* __restrict__ bih, const float* __restrict__ bhh,
            const float* __restrict__ bq,  const float* __restrict__ bk,
            const float* __restrict__ bv,  const float* __restrict__ bfuse,
            float* __restrict__ out)
{
    extern __shared__ __align__(16) char smem[];
    uint2* sWg = (uint2*)smem;
    uint2* sWq = (uint2*)(smem + SOFF_WQ);
    uint2* sWf = (uint2*)(smem + SOFF_WF);
    uint4* sA  = (uint4*)(smem + SOFF_A);
    const float** rowp = (const float**)(smem + SOFF_RP);

    const int idx0   = blockIdx.x * blockDim.x + threadIdx.x;
    const int stride = gridDim.x * blockDim.x;
    const int bid    = blockIdx.x;
    const int nblk   = gridDim.x;
    const int tid    = threadIdx.x;

    // ---- prologue: pin weights, init state, base GEMM --------------------
    if (bid < 144) {
        const uint4* s1 = (const uint4*)(WbaseF + (size_t)bid * TSK_G);
        for (int i = tid; i < TSK_G / 2; i += NTHREADS) ((uint4*)sWg)[i] = s1[i];
        const uint4* s2 = (const uint4*)(WqF + (size_t)bid * TSK_Q);
        for (int i = tid; i < TSK_Q / 2; i += NTHREADS) ((uint4*)sWq)[i] = s2[i];
        const uint4* s3 = (const uint4*)(WfF + (size_t)bid * TSK_F);
        for (int i = tid; i < TSK_F / 2; i += NTHREADS) ((uint4*)sWf)[i] = s3[i];
    }
    for (int idx = idx0; idx < B_ * H_; idx += stride) {
        g_h[idx] = h0[idx];
        g_c[idx] = c0[idx];
        g_newvAll[idx] = x[idx];
    }
    __syncthreads();

    if (bid < 144) {
        const int nt = bid / 6, kc = bid % 6;
        const float* Ab = (kc < 3) ? (question + kc * 256) : (answer + (kc - 3) * 256);
        float acc[4][4] = {};
        stageA_g(sA, 0, Ab, H_, 0);
        __syncthreads();
        for (int s = 0; s < 8; s++) {
            if (s < 7) stageA_g(sA, (s + 1) & 1, Ab, H_, (s + 1) * 32);
            comp_stage<2, 4, 4, 4, 16>(sA, sWg, s & 1, s, acc);
            __syncthreads();
        }
        epi<4, 4>(acc, g_gp + (size_t)kc * (B_ * G4H) + nt * 128, G4H);
        __syncthreads();
        const uint4* s1 = (const uint4*)(WgF + (size_t)bid * TSK_G);
        for (int i = tid; i < TSK_G / 2; i += NTHREADS) ((uint4*)sWg)[i] = s1[i];
    }
    gsync();

    for (int idx = idx0; idx < B_ * G4H; idx += stride) {
        int n = idx % G4H;
        float s = bqh[n] + bah[n] + bih[n] + bhh[n];
        #pragma unroll
        for (int kc = 0; kc < SK_G; kc++) s += g_gp[(size_t)kc * (B_ * G4H) + idx];
        g_base[idx] = s;
    }
    gsync();

    // =======================================================================
    for (int t = 0; t < T_; t++) {
        // ---- X: gates(t) + QKV(t+1) on pinned weights ---------------------
        if (bid < 144) {
            {
                const int nt = bid / 6, kc = bid % 6;
                const float* Ab = (kc < 3) ? (g_newvAll + (size_t)t * (B_ * H_) + kc * 256)
                                           : (g_h + (kc - 3) * 256);
                float acc[4][4] = {};
                stageA_g(sA, 0, Ab, H_, 0);
                __syncthreads();
                for (int s = 0; s < 8; s++) {
                    if (s < 7) stageA_g(sA, (s + 1) & 1, Ab, H_, (s + 1) * 32);
                    comp_stage<2, 4, 4, 4, 16>(sA, sWg, s & 1, s, acc);
                    __syncthreads();
                }
                epi<4, 4>(acc, g_gp + (size_t)kc * (B_ * G4H) + nt * 128, G4H);
                __syncthreads();
            }
            if (t + 1 < T_) {
                if (tid < 128) {
                    int m = tid, b = m >> 1, s2 = m & 1;
                    const float* p;
                    if (s2) {
                        p = x + ((size_t)(t + 1) * B_ + b) * H_;
                    } else {
                        int pt = ping[b * T_ + (t + 1)];
                        int i2 = pt - 1;
                        i2 = i2 < 0 ? 0 : (i2 > T_ - 1 ? T_ - 1 : i2);
                        p = ((i2 <= t) ? g_newvAll : x) + ((size_t)i2 * B_ + b) * H_;
                    }
                    rowp[m] = p;
                }
                __syncthreads();
                const int nt = bid / 4, kc = bid % 4;
                const int c0 = kc * 192;
                float acc[4][4] = {};
                stageA_q(sA, 0, rowp, c0);
                __syncthreads();
                for (int s = 0; s < 12; s++) {
                    if (s < 11) stageA_q(sA, (s + 1) & 1, rowp, c0 + (s + 1) * 16);
                    comp_stage<1, 8, 2, 4, 8>(sA, sWq, s & 1, s, acc);
                    __syncthreads();
                }
                epi<2, 4>(acc, g_qkvp + (size_t)kc * (2 * B_ * QKVW) + nt * 64, QKVW);
            }
        }
        gsync();

        // ---- Y: attention(t+1) + LSTM pointwise(t) -------------------------
        if (t + 1 < T_) {
            int wid = bid * (NTHREADS / 32) + (tid >> 5);
            int lane = tid & 31;
            for (int task = wid; task < B_ * NH_; task += nblk * (NTHREADS / 32)) {
                int b = task / NH_, h = task - b * NH_;
                float q[2][2], kk2[2][2], vv[2][2];
                #pragma unroll
                for (int s = 0; s < 2; s++) {
                    int row = (b * 2 + s) * QKVW;
                    #pragma unroll
                    for (int dd = 0; dd < 2; dd++) {
                        int col = h * HD_ + lane + dd * 32;
                        float qv = bq[col], kv = bk[col], vvv = bv[col];
                        #pragma unroll
                        for (int kc = 0; kc < SK_Q; kc++) {
                            const float* p = g_qkvp + (size_t)kc * (2 * B_ * QKVW) + row;
                            qv  += p[col];
                            kv  += p[H_ + col];
                            vvv += p[2 * H_ + col];
                        }
                        q[s][dd] = qv; kk2[s][dd] = kv; vv[s][dd] = vvv;
                    }
                }
                float s00 = wsum(q[0][0]*kk2[0][0] + q[0][1]*kk2[0][1]) * 0.125f;
                float s01 = wsum(q[0][0]*kk2[1][0] + q[0][1]*kk2[1][1]) * 0.125f;
                float s10 = wsum(q[1][0]*kk2[0][0] + q[1][1]*kk2[0][1]) * 0.125f;
                float s11 = wsum(q[1][0]*kk2[1][0] + q[1][1]*kk2[1][1]) * 0.125f;
                float m0 = fmaxf(s00, s01), m1 = fmaxf(s10, s11);
                float e00 = expf(s00 - m0), e01 = expf(s01 - m0);
                float e10 = expf(s10 - m1), e11 = expf(s11 - m1);
                float r0 = 1.f / (e00 + e01), r1 = 1.f / (e10 + e11);
                float p00 = e00 * r0, p01 = e01 * r0, p10 = e10 * r1, p11 = e11 * r1;
                #pragma unroll
                for (int dd = 0; dd < 2; dd++) {
                    int d = lane + dd * 32;
                    g_ctx[b * (2*H_) + h * HD_ + d]      = p00 * vv[0][dd] + p01 * vv[1][dd];
                    g_ctx[b * (2*H_) + H_ + h * HD_ + d] = p10 * vv[0][dd] + p11 * vv[1][dd];
                }
            }
        }
        for (int idx = idx0; idx < B_ * H_; idx += stride) {
            int b = idx / H_, j = idx - b * H_;
            float gg[4];
            #pragma unroll
            for (int u = 0; u < 4; u++) {
                int col = b * G4H + u * H_ + j;
                float s = g_base[col];
                #pragma unroll
                for (int kc = 0; kc < SK_G; kc++) s += g_gp[(size_t)kc * (B_ * G4H) + col];
                gg[u] = s;
            }
            float iv = sigm(gg[0]);
            float fv = sigm(gg[1]);
            float gv = tanhf(gg[2]);
            float ov = sigm(gg[3]);
            float c = fv * g_c[idx] + iv * gv;
            float h = ov * tanhf(c);
            g_c[idx] = c;
            g_h[idx] = h;
            out[((size_t)t * B_ + b) * H_ + j] = h;
            if (t == T_ - 1) {
                out[((size_t)T_ * B_ + b) * H_ + j]       = h;
                out[((size_t)(T_ + 1) * B_ + b) * H_ + j] = c;
            }
        }
        gsync();

        if (t + 1 < T_) {
            // ---- Z: fuse(t+1) on pinned weights ------------------------------
            if (bid < 144) {
                const int nt = bid / 12, kc = bid % 12;
                const float* Ab = g_ctx + kc * 128;
                float acc[2][4] = {};
                stageA_g(sA, 0, Ab, 2 * H_, 0);
                __syncthreads();
                for (int s = 0; s < 4; s++) {
                    if (s < 3) stageA_g(sA, (s + 1) & 1, Ab, 2 * H_, (s + 1) * 32);
                    comp_stage<2, 4, 4, 2, 8>(sA, sWf, s & 1, s, acc);
                    __syncthreads();
                }
                epi<4, 2>(acc, g_fp + (size_t)kc * (B_ * H_) + nt * 64, H_);
            }
            gsync();

            // ---- W: combine fuse + select -> newv(t+1) ------------------------
            for (int idx = idx0; idx < B_ * H_; idx += stride) {
                int b = idx / H_, j = idx - b * H_;
                float e = bfuse[j];
                #pragma unroll
                for (int kc = 0; kc < SK_F; kc++) e += g_fp[(size_t)kc * (B_ * H_) + idx];
                int pt = ping[b * T_ + (t + 1)];
                float right = x[((size_t)(t + 1) * B_ + b) * H_ + j];
                g_newvAll[(size_t)(t + 1) * (B_ * H_) + idx] = (pt > 0) ? e : right;
            }
            gsync();
        }
    }
}

extern "C" void kernel_launch(void* const* d_in, const int* in_sizes, int n_in,
                              void* d_out, int out_size)
{
    (void)in_sizes; (void)n_in; (void)out_size;
    const float* question = (const float*)d_in[0];
    const float* answer   = (const float*)d_in[1];
    const float* x        = (const float*)d_in[2];
    const int*   ping     = (const int*)  d_in[3];
    const float* h0       = (const float*)d_in[4];
    const float* c0       = (const float*)d_in[5];
    const float* Wqh      = (const float*)d_in[6];
    const float* bqh      = (const float*)d_in[7];
    const float* Wah      = (const float*)d_in[8];
    const float* bah      = (const float*)d_in[9];
    const float* Wih      = (const float*)d_in[10];
    const float* bih      = (const float*)d_in[11];
    const float* Whh      = (const float*)d_in[12];
    const float* bhh      = (const float*)d_in[13];
    const float* Wq       = (const float*)d_in[14];
    const float* bq       = (const float*)d_in[15];
    const float* Wk       = (const float*)d_in[16];
    const float* bk       = (const float*)d_in[17];
    const float* Wv       = (const float*)d_in[18];
    const float* bv       = (const float*)d_in[19];
    const float* Wfuse    = (const float*)d_in[20];
    const float* bfuse    = (const float*)d_in[21];

    int dev = 0;
    cudaGetDevice(&dev);
    int nsm = 148;
    cudaDeviceGetAttribute(&nsm, cudaDevAttrMultiProcessorCount, dev);

    cudaFuncSetAttribute(sqac_kernel, cudaFuncAttributeMaxDynamicSharedMemorySize, SMEM_TOTAL);

    prep_kernel<<<nsm * 8, 256>>>(Wqh, Wah, Wih, Whh, Wq, Wk, Wv, Wfuse);
    sqac_kernel<<<nsm, NTHREADS, SMEM_TOTAL>>>(question, answer, x, ping, h0, c0,
                                               bqh, bah, bih, bhh, bq, bk, bv, bfuse,
                                               (float*)d_out);
}